// round 2
// baseline (speedup 1.0000x reference)
#include <cuda_runtime.h>
#include <math.h>

#define HW   16384
#define W_   128
#define H_   128
#define C_   128
#define B_   2
#define ITERS 10

// ---------------- scratch (static device globals; no allocation) ----------------
__device__ float g_tmp [B_*C_*HW];     // conv intermediate, NCHW
__device__ float g_lf0 [B_*HW*C_];     // NHWC
__device__ float g_lf1 [B_*HW*C_];     // NHWC
__device__ float g_f1t [B_*HW*C_];     // feat1 transposed to NHWC
__device__ float g_feat[B_*HW*C_];     // NHWC (1 - normalized diff)
__device__ float g_q   [B_*HW*C_];     // NHWC
__device__ float g_k   [B_*HW*C_];     // NHWC
__device__ float g_fi  [B_*2*HW];      // NCHW
__device__ float g_d1  [B_*16*HW];
__device__ float g_d2  [B_*16*HW];
__device__ float g_flow[B_*2*HW];      // NCHW
__device__ float g_hcat[B_*258*HW];    // NCHW
__device__ float g_h1  [B_*C_*HW];
__device__ float g_h2  [B_*64*HW];

__device__ __forceinline__ float gelu_f(float x) {
    return 0.5f * x * (1.0f + erff(x * 0.70710678118654752440f));
}

// ---------------- generic tiled 3x3 conv (NCHW in, NCHW or NHWC out) ----------------
// block = 16x16 pixels, 16 output channels per block. ACT: 0 none, 1 gelu.
template<int ACT, int OUTNHWC>
__global__ __launch_bounds__(256)
void conv3_tiled(const float* __restrict__ in, const float* __restrict__ w,
                 const float* __restrict__ bias, float* __restrict__ out,
                 int Cin, int Cout)
{
    __shared__ float  s_in[18][20];
    __shared__ float4 s_w[16][3];

    int nz  = Cout >> 4;
    int b   = blockIdx.z / nz;
    int co0 = (blockIdx.z - b * nz) << 4;
    int x0  = blockIdx.x << 4;
    int y0  = blockIdx.y << 4;
    int tx  = threadIdx.x, ty = threadIdx.y;
    int tid = (ty << 4) + tx;

    float acc[16];
#pragma unroll
    for (int i = 0; i < 16; i++) acc[i] = 0.f;

    const float* ip = in + (size_t)b * Cin * HW;
    const float* wp = w + (size_t)co0 * Cin * 9;

    for (int ci = 0; ci < Cin; ci++) {
        // stage 18x18 input tile (zero padded)
#pragma unroll
        for (int t = tid; t < 324; t += 256) {
            int iy = t / 18, ix = t - iy * 18;
            int gy = y0 + iy - 1, gx = x0 + ix - 1;
            float v = 0.f;
            if ((unsigned)gy < 128u && (unsigned)gx < 128u) v = ip[gy * W_ + gx];
            s_in[iy][ix] = v;
        }
        // stage 16 x 9 weights into padded rows of 12 floats (float4-readable)
        if (tid < 144) {
            int co = tid / 9, kk = tid - co * 9;
            ((float*)s_w)[co * 12 + kk] = wp[(size_t)co * Cin * 9 + kk];
        }
        __syncthreads();

        float v0 = s_in[ty + 0][tx + 0], v1 = s_in[ty + 0][tx + 1], v2 = s_in[ty + 0][tx + 2];
        float v3 = s_in[ty + 1][tx + 0], v4 = s_in[ty + 1][tx + 1], v5 = s_in[ty + 1][tx + 2];
        float v6 = s_in[ty + 2][tx + 0], v7 = s_in[ty + 2][tx + 1], v8 = s_in[ty + 2][tx + 2];

#pragma unroll
        for (int co = 0; co < 16; co++) {
            float4 w0 = s_w[co][0], w1 = s_w[co][1], w2 = s_w[co][2];
            acc[co] += v0 * w0.x + v1 * w0.y + v2 * w0.z + v3 * w0.w
                     + v4 * w1.x + v5 * w1.y + v6 * w1.z + v7 * w1.w
                     + v8 * w2.x;
        }
        __syncthreads();
        ip += HW; wp += 9;
    }

    int y = y0 + ty, x = x0 + tx, p = y * W_ + x;
#pragma unroll
    for (int co = 0; co < 16; co++) {
        float r = acc[co] + bias[co0 + co];
        if (ACT == 1) r = gelu_f(r);
        if (OUTNHWC) out[((size_t)(b * HW) + p) * Cout + co0 + co] = r;
        else         out[((size_t)(b * Cout) + co0 + co) * HW + p] = r;
    }
}

// ---------------- small direct 3x3 conv (tiny channel counts) ----------------
// ACT: 0 none, 1 gelu, 2 sigmoid, 3 add-to-output-in-place (flow += conv)
template<int CIN, int COUT, int ACT>
__global__ void conv3_small(const float* __restrict__ in, const float* __restrict__ w,
                            const float* __restrict__ bias, float* __restrict__ out)
{
    int idx = blockIdx.x * blockDim.x + threadIdx.x;
    if (idx >= B_ * COUT * HW) return;
    int p  = idx % HW;
    int co = (idx / HW) % COUT;
    int b  = idx / (HW * COUT);
    int y = p >> 7, x = p & 127;

    float acc = bias[co];
    const float* ip = in + (size_t)b * CIN * HW;
    const float* wp = w + (size_t)co * CIN * 9;
#pragma unroll 4
    for (int ci = 0; ci < CIN; ci++) {
#pragma unroll
        for (int ky = 0; ky < 3; ky++) {
            int yy = y + ky - 1;
            if ((unsigned)yy < 128u) {
#pragma unroll
                for (int kx = 0; kx < 3; kx++) {
                    int xx = x + kx - 1;
                    if ((unsigned)xx < 128u)
                        acc += ip[ci * HW + yy * W_ + xx] * wp[ci * 9 + ky * 3 + kx];
                }
            }
        }
    }
    if (ACT == 1) acc = gelu_f(acc);
    if (ACT == 2) acc = 1.0f / (1.0f + expf(-acc));
    if (ACT == 3) acc = out[idx] + acc;
    out[idx] = acc;
}

// ---------------- q/k GEMM: Out[p,d] = sum_c feat[p,c] * W[d,c] + b[d] ----------------
// M=32768, N=128, K=128. Block: 128x128 tile, 256 threads, 8x8 microtile.
__global__ __launch_bounds__(256)
void qk_gemm(const float* __restrict__ A,
             const float* __restrict__ Wq, const float* __restrict__ Bq,
             const float* __restrict__ Wk, const float* __restrict__ Bk,
             float* __restrict__ Qo, float* __restrict__ Ko)
{
    __shared__ float As[8][132];
    __shared__ float Bs[8][132];

    const float* Wm   = blockIdx.y ? Wk : Wq;
    const float* Bias = blockIdx.y ? Bk : Bq;
    float*       Out  = blockIdx.y ? Ko : Qo;

    int m0  = blockIdx.x << 7;
    int tid = threadIdx.x;
    int mr  = (tid >> 4) << 3;
    int nr  = (tid & 15) << 3;

    float acc[8][8];
#pragma unroll
    for (int i = 0; i < 8; i++)
#pragma unroll
        for (int j = 0; j < 8; j++) acc[i][j] = 0.f;

    int lr = tid >> 1;
    int lk = (tid & 1) << 2;

    for (int kc = 0; kc < 128; kc += 8) {
        float4 av = *(const float4*)(A  + (size_t)(m0 + lr) * 128 + kc + lk);
        float4 bv = *(const float4*)(Wm + (size_t)lr * 128 + kc + lk);
        As[lk + 0][lr] = av.x; As[lk + 1][lr] = av.y; As[lk + 2][lr] = av.z; As[lk + 3][lr] = av.w;
        Bs[lk + 0][lr] = bv.x; Bs[lk + 1][lr] = bv.y; Bs[lk + 2][lr] = bv.z; Bs[lk + 3][lr] = bv.w;
        __syncthreads();
#pragma unroll
        for (int kk = 0; kk < 8; kk++) {
            float4 a0 = *(const float4*)&As[kk][mr];
            float4 a1 = *(const float4*)&As[kk][mr + 4];
            float4 b0 = *(const float4*)&Bs[kk][nr];
            float4 b1 = *(const float4*)&Bs[kk][nr + 4];
            float a[8] = {a0.x, a0.y, a0.z, a0.w, a1.x, a1.y, a1.z, a1.w};
            float bb[8] = {b0.x, b0.y, b0.z, b0.w, b1.x, b1.y, b1.z, b1.w};
#pragma unroll
            for (int i = 0; i < 8; i++)
#pragma unroll
                for (int j = 0; j < 8; j++) acc[i][j] += a[i] * bb[j];
        }
        __syncthreads();
    }

    float bn[8];
#pragma unroll
    for (int j = 0; j < 8; j++) bn[j] = Bias[nr + j];
#pragma unroll
    for (int i = 0; i < 8; i++) {
        float4 r0 = make_float4(acc[i][0] + bn[0], acc[i][1] + bn[1], acc[i][2] + bn[2], acc[i][3] + bn[3]);
        float4 r1 = make_float4(acc[i][4] + bn[4], acc[i][5] + bn[5], acc[i][6] + bn[6], acc[i][7] + bn[7]);
        *(float4*)(Out + (size_t)(m0 + mr + i) * 128 + nr)     = r0;
        *(float4*)(Out + (size_t)(m0 + mr + i) * 128 + nr + 4) = r1;
    }
}

// ---------------- warp-per-pixel: bilinear warp + diff + L2 normalize + (1 - .) ----------------
__global__ void warp_diff_norm(const float* __restrict__ lf0, const float* __restrict__ lf1,
                               const float* __restrict__ flow, float* __restrict__ feat)
{
    int gw   = (blockIdx.x * blockDim.x + threadIdx.x) >> 5;
    int lane = threadIdx.x & 31;
    int b = gw >> 14;          // gw / HW
    int p = gw & (HW - 1);
    int y = p >> 7, x = p & 127;

    float fx = flow[(size_t)(b * 2) * HW + p];
    float fy = flow[(size_t)(b * 2 + 1) * HW + p];
    float xf = fminf(fmaxf((float)x + fx, 0.f), 127.f);
    float yf = fminf(fmaxf((float)y + fy, 0.f), 127.f);
    float x0f = floorf(xf), y0f = floorf(yf);
    int x0 = (int)x0f, y0 = (int)y0f;
    int x1 = min(x0 + 1, 127), y1 = min(y0 + 1, 127);
    float wx = xf - x0f, wy = yf - y0f;

    const float* base = lf1 + (size_t)b * HW * C_;
    int c4 = lane * 4;
    float4 v00 = *(const float4*)(base + (size_t)(y0 * W_ + x0) * C_ + c4);
    float4 v01 = *(const float4*)(base + (size_t)(y0 * W_ + x1) * C_ + c4);
    float4 v10 = *(const float4*)(base + (size_t)(y1 * W_ + x0) * C_ + c4);
    float4 v11 = *(const float4*)(base + (size_t)(y1 * W_ + x1) * C_ + c4);

    float w00 = (1.f - wx) * (1.f - wy), w01 = wx * (1.f - wy);
    float w10 = (1.f - wx) * wy,         w11 = wx * wy;

    float4 l0 = *(const float4*)(lf0 + (size_t)gw * C_ + c4);
    float dx0 = l0.x - (v00.x * w00 + v01.x * w01 + v10.x * w10 + v11.x * w11);
    float dx1 = l0.y - (v00.y * w00 + v01.y * w01 + v10.y * w10 + v11.y * w11);
    float dx2 = l0.z - (v00.z * w00 + v01.z * w01 + v10.z * w10 + v11.z * w11);
    float dx3 = l0.w - (v00.w * w00 + v01.w * w01 + v10.w * w10 + v11.w * w11);

    float ss = dx0 * dx0 + dx1 * dx1 + dx2 * dx2 + dx3 * dx3;
#pragma unroll
    for (int o = 16; o; o >>= 1) ss += __shfl_xor_sync(0xffffffffu, ss, o);
    float scale = 1.0f / fmaxf(sqrtf(ss), 1e-12f);

    float4 r = make_float4(1.f - dx0 * scale, 1.f - dx1 * scale,
                           1.f - dx2 * scale, 1.f - dx3 * scale);
    *(float4*)(feat + (size_t)gw * C_ + c4) = r;
}

// ---------------- warp-per-pixel: 25-tap local attention on flow ----------------
__global__ void attn_kernel(const float* __restrict__ q, const float* __restrict__ k,
                            const float* __restrict__ flow, float* __restrict__ fi)
{
    int gw   = (blockIdx.x * blockDim.x + threadIdx.x) >> 5;
    int lane = threadIdx.x & 31;
    int b = gw >> 14;
    int p = gw & (HW - 1);
    int y = p >> 7, x = p & 127;

    float4 qv = *(const float4*)(q + (size_t)gw * C_ + lane * 4);

    float myscore = -INFINITY;
#pragma unroll
    for (int t = 0; t < 25; t++) {
        int dy = t / 5 - 2, dx = t % 5 - 2;
        int yy = y + dy, xx = x + dx;
        float s = 0.f;
        if ((unsigned)yy < 128u && (unsigned)xx < 128u) {
            float4 kv = *(const float4*)(k + (size_t)(b * HW + yy * W_ + xx) * C_ + lane * 4);
            s = qv.x * kv.x + qv.y * kv.y + qv.z * kv.z + qv.w * kv.w;
        }
#pragma unroll
        for (int o = 16; o; o >>= 1) s += __shfl_xor_sync(0xffffffffu, s, o);
        if (lane == t) myscore = s * 0.088388347648318447f;  // 1/sqrt(128)
    }
    // softmax across the 25 lanes holding scores
    float m = myscore;
#pragma unroll
    for (int o = 16; o; o >>= 1) m = fmaxf(m, __shfl_xor_sync(0xffffffffu, m, o));
    float e = (lane < 25) ? expf(myscore - m) : 0.f;
    float ssum = e;
#pragma unroll
    for (int o = 16; o; o >>= 1) ssum += __shfl_xor_sync(0xffffffffu, ssum, o);
    float prob = e / ssum;

    float a0 = 0.f, a1 = 0.f;
    if (lane < 25) {
        int dy = lane / 5 - 2, dx = lane % 5 - 2;
        int yy = y + dy, xx = x + dx;
        if ((unsigned)yy < 128u && (unsigned)xx < 128u) {
            a0 = prob * flow[(size_t)(b * 2) * HW + yy * W_ + xx];
            a1 = prob * flow[(size_t)(b * 2 + 1) * HW + yy * W_ + xx];
        }
    }
#pragma unroll
    for (int o = 16; o; o >>= 1) {
        a0 += __shfl_xor_sync(0xffffffffu, a0, o);
        a1 += __shfl_xor_sync(0xffffffffu, a1, o);
    }
    if (lane == 0) {
        fi[(size_t)(b * 2) * HW + p]     = a0;
        fi[(size_t)(b * 2 + 1) * HW + p] = a1;
    }
}

// ---------------- warp feat1 (NHWC) into hcat channels [128,256) (NCHW) ----------------
__global__ void warp_hcat(const float* __restrict__ src, const float* __restrict__ flow,
                          float* __restrict__ hcat)
{
    int gw   = (blockIdx.x * blockDim.x + threadIdx.x) >> 5;
    int lane = threadIdx.x & 31;
    int b = gw >> 14;
    int p = gw & (HW - 1);
    int y = p >> 7, x = p & 127;

    float fx = flow[(size_t)(b * 2) * HW + p];
    float fy = flow[(size_t)(b * 2 + 1) * HW + p];
    float xf = fminf(fmaxf((float)x + fx, 0.f), 127.f);
    float yf = fminf(fmaxf((float)y + fy, 0.f), 127.f);
    float x0f = floorf(xf), y0f = floorf(yf);
    int x0 = (int)x0f, y0 = (int)y0f;
    int x1 = min(x0 + 1, 127), y1 = min(y0 + 1, 127);
    float wx = xf - x0f, wy = yf - y0f;

    const float* base = src + (size_t)b * HW * C_;
    int c4 = lane * 4;
    float4 v00 = *(const float4*)(base + (size_t)(y0 * W_ + x0) * C_ + c4);
    float4 v01 = *(const float4*)(base + (size_t)(y0 * W_ + x1) * C_ + c4);
    float4 v10 = *(const float4*)(base + (size_t)(y1 * W_ + x0) * C_ + c4);
    float4 v11 = *(const float4*)(base + (size_t)(y1 * W_ + x1) * C_ + c4);

    float w00 = (1.f - wx) * (1.f - wy), w01 = wx * (1.f - wy);
    float w10 = (1.f - wx) * wy,         w11 = wx * wy;

    float o0 = v00.x * w00 + v01.x * w01 + v10.x * w10 + v11.x * w11;
    float o1 = v00.y * w00 + v01.y * w01 + v10.y * w10 + v11.y * w11;
    float o2 = v00.z * w00 + v01.z * w01 + v10.z * w10 + v11.z * w11;
    float o3 = v00.w * w00 + v01.w * w01 + v10.w * w10 + v11.w * w11;

    size_t baseo = ((size_t)b * 258 + 128 + c4) * HW + p;
    hcat[baseo]            = o0;
    hcat[baseo + HW]       = o1;
    hcat[baseo + 2 * HW]   = o2;
    hcat[baseo + 3 * HW]   = o3;
}

// ---------------- misc ----------------
__global__ void copy_kernel(const float* __restrict__ in, float* __restrict__ out, int n)
{
    int i = blockIdx.x * blockDim.x + threadIdx.x;
    if (i < n) out[i] = in[i];
}

__global__ void transpose_nhwc(const float* __restrict__ in, float* __restrict__ out)
{
    int idx = blockIdx.x * blockDim.x + threadIdx.x;
    if (idx >= B_ * C_ * HW) return;
    int p = idx & (HW - 1);
    int c = (idx >> 14) & 127;
    int b = idx >> 21;
    out[((size_t)(b * HW) + p) * C_ + c] = in[idx];
}

__global__ void hcat_fill(const float* __restrict__ feat0, const float* __restrict__ flow,
                          float* __restrict__ hcat)
{
    int idx = blockIdx.x * blockDim.x + threadIdx.x;
    if (idx >= B_ * 130 * HW) return;
    int p = idx % HW;
    int c = (idx / HW) % 130;
    int b = idx / (130 * HW);
    if (c < 128) {
        hcat[((size_t)b * 258 + c) * HW + p] = feat0[((size_t)b * 128 + c) * HW + p];
    } else {
        int f = c - 128;
        hcat[((size_t)b * 258 + 256 + f) * HW + p] = flow[((size_t)b * 2 + f) * HW + p];
    }
}

// ---------------- launch ----------------
extern "C" void kernel_launch(void* const* d_in, const int* in_sizes, int n_in,
                              void* d_out, int out_size)
{
    const float* feat0     = (const float*)d_in[0];
    const float* feat1     = (const float*)d_in[1];
    const float* flow_init = (const float*)d_in[2];
    const float* lc_w1 = (const float*)d_in[3];
    const float* lc_b1 = (const float*)d_in[4];
    const float* lc_w2 = (const float*)d_in[5];
    const float* lc_b2 = (const float*)d_in[6];
    const float* qw    = (const float*)d_in[7];
    const float* qb    = (const float*)d_in[8];
    const float* kw    = (const float*)d_in[9];
    const float* kb    = (const float*)d_in[10];
    const float* fr_w1 = (const float*)d_in[11];
    const float* fr_b1 = (const float*)d_in[12];
    const float* fr_w2 = (const float*)d_in[13];
    const float* fr_b2 = (const float*)d_in[14];
    const float* fr_w3 = (const float*)d_in[15];
    const float* fr_b3 = (const float*)d_in[16];
    const float* cf_w1 = (const float*)d_in[17];
    const float* cf_b1 = (const float*)d_in[18];
    const float* cf_w2 = (const float*)d_in[19];
    const float* cf_b2 = (const float*)d_in[20];
    const float* cf_w3 = (const float*)d_in[21];
    const float* cf_b3 = (const float*)d_in[22];
    float* out = (float*)d_out;

    float *p_tmp, *p_lf0, *p_lf1, *p_f1t, *p_feat, *p_q, *p_k;
    float *p_fi, *p_d1, *p_d2, *p_flow, *p_hcat, *p_h1, *p_h2;
    cudaGetSymbolAddress((void**)&p_tmp,  g_tmp);
    cudaGetSymbolAddress((void**)&p_lf0,  g_lf0);
    cudaGetSymbolAddress((void**)&p_lf1,  g_lf1);
    cudaGetSymbolAddress((void**)&p_f1t,  g_f1t);
    cudaGetSymbolAddress((void**)&p_feat, g_feat);
    cudaGetSymbolAddress((void**)&p_q,    g_q);
    cudaGetSymbolAddress((void**)&p_k,    g_k);
    cudaGetSymbolAddress((void**)&p_fi,   g_fi);
    cudaGetSymbolAddress((void**)&p_d1,   g_d1);
    cudaGetSymbolAddress((void**)&p_d2,   g_d2);
    cudaGetSymbolAddress((void**)&p_flow, g_flow);
    cudaGetSymbolAddress((void**)&p_hcat, g_hcat);
    cudaGetSymbolAddress((void**)&p_h1,   g_h1);
    cudaGetSymbolAddress((void**)&p_h2,   g_h2);

    dim3 cb(16, 16);
    dim3 cg128(8, 8, B_ * 8);   // Cout=128 -> 8 groups of 16
    dim3 cg64 (8, 8, B_ * 4);   // Cout=64

    // local_conv chain (hoisted): lf0, lf1 in NHWC
    conv3_tiled<1, 0><<<cg128, cb>>>(feat0, lc_w1, lc_b1, p_tmp, 128, 128);
    conv3_tiled<0, 1><<<cg128, cb>>>(p_tmp, lc_w2, lc_b2, p_lf0, 128, 128);
    conv3_tiled<1, 0><<<cg128, cb>>>(feat1, lc_w1, lc_b1, p_tmp, 128, 128);
    conv3_tiled<0, 1><<<cg128, cb>>>(p_tmp, lc_w2, lc_b2, p_lf1, 128, 128);
    transpose_nhwc<<<(B_ * C_ * HW) / 256, 256>>>(feat1, p_f1t);
    copy_kernel<<<(B_ * 2 * HW) / 256, 256>>>(flow_init, p_flow, B_ * 2 * HW);

    for (int it = 0; it < ITERS; it++) {
        warp_diff_norm<<<(B_ * HW) / 4, 128>>>(p_lf0, p_lf1, p_flow, p_feat);
        qk_gemm<<<dim3((B_ * HW) / 128, 2), 256>>>(p_feat, qw, qb, kw, kb, p_q, p_k);
        attn_kernel<<<(B_ * HW) / 4, 128>>>(p_q, p_k, p_flow, p_fi);
        conv3_small<2, 16, 1><<<(B_ * 16 * HW + 255) / 256, 256>>>(p_fi, fr_w1, fr_b1, p_d1);
        conv3_small<16, 16, 1><<<(B_ * 16 * HW + 255) / 256, 256>>>(p_d1, fr_w2, fr_b2, p_d2);
        conv3_small<16, 2, 3><<<(B_ * 2 * HW + 255) / 256, 256>>>(p_d2, fr_w3, fr_b3, p_flow);
    }

    // confidence head
    hcat_fill<<<(B_ * 130 * HW + 255) / 256, 256>>>(feat0, p_flow, p_hcat);
    warp_hcat<<<(B_ * HW) / 4, 128>>>(p_f1t, p_flow, p_hcat);
    conv3_tiled<1, 0><<<cg128, cb>>>(p_hcat, cf_w1, cf_b1, p_h1, 258, 128);
    conv3_tiled<1, 0><<<cg64,  cb>>>(p_h1,  cf_w2, cf_b2, p_h2, 128, 64);
    conv3_small<64, 1, 2><<<(B_ * HW + 255) / 256, 256>>>(p_h2, cf_w3, cf_b3, out + B_ * 2 * HW);

    // outputs: flow then conf
    copy_kernel<<<(B_ * 2 * HW) / 256, 256>>>(p_flow, out, B_ * 2 * HW);
}

// round 5
// speedup vs baseline: 1.0518x; 1.0518x over previous
#include <cuda_runtime.h>
#include <math.h>

#define HW   16384
#define W_   128
#define H_   128
#define C_   128
#define B_   2
#define ITERS 10

// ---------------- scratch (static device globals; no allocation) ----------------
__device__ float g_tmp [B_*C_*HW];     // conv intermediate, NCHW
__device__ float g_lf0 [B_*HW*C_];     // NHWC
__device__ float g_lf1 [B_*HW*C_];     // NHWC
__device__ float g_f1t [B_*HW*C_];     // feat1 transposed to NHWC
__device__ float g_feat[B_*HW*C_];     // NHWC (1 - normalized diff)
__device__ float g_q   [B_*HW*C_];     // NHWC
__device__ float g_k   [B_*HW*C_];     // NHWC
__device__ float g_fi  [B_*2*HW];      // NCHW
__device__ float g_d1  [B_*16*HW];
__device__ float g_d2  [B_*16*HW];
__device__ float g_flow[B_*2*HW];      // NCHW
__device__ float g_hcat[B_*258*HW];    // NCHW
__device__ float g_h1  [B_*C_*HW];
__device__ float g_h2  [B_*64*HW];

__device__ __forceinline__ float gelu_f(float x) {
    return 0.5f * x * (1.0f + erff(x * 0.70710678118654752440f));
}

// ---------------- packed f32x2 helpers (Blackwell FFMA2 path) ----------------
typedef unsigned long long u64t;

__device__ __forceinline__ u64t pk2(float lo, float hi) {
    u64t r; asm("mov.b64 %0, {%1,%2};" : "=l"(r) : "f"(lo), "f"(hi)); return r;
}
__device__ __forceinline__ void fma2(u64t& d, u64t a, u64t b) {
    asm("fma.rn.f32x2 %0, %1, %2, %0;" : "+l"(d) : "l"(a), "l"(b));
}
__device__ __forceinline__ float2 unpk(u64t v) {
    float2 r; asm("mov.b64 {%0,%1}, %2;" : "=f"(r.x), "=f"(r.y) : "l"(v)); return r;
}

// ---------------- 3x3 conv v2: 32x32 px tile, 2x2 px/thread, 8 co/block ----------------
// NCHW in. ACT: 0 none, 1 gelu. OUTNHWC: 0 NCHW, 1 NHWC. Cin even, Cout % 8 == 0.
template<int ACT, int OUTNHWC>
__global__ __launch_bounds__(256, 2)
void conv3_v2(const float* __restrict__ in, const float* __restrict__ w,
              const float* __restrict__ bias, float* __restrict__ out,
              int Cin, int Cout)
{
    __shared__ float s_in[2][34][36];
    __shared__ float s_w[2][8][12];

    int nz  = Cout >> 3;
    int b   = blockIdx.z / nz;
    int co0 = (blockIdx.z - b * nz) << 3;
    int x0  = blockIdx.x << 5;
    int y0  = blockIdx.y << 5;
    int tid = threadIdx.x;
    int tx  = tid & 15, ty = tid >> 4;

    u64t acc[8][2];
#pragma unroll
    for (int co = 0; co < 8; co++) { acc[co][0] = 0ull; acc[co][1] = 0ull; }

    const float* ip = in + (size_t)b * Cin * HW;
    const float* wp = w + (size_t)co0 * Cin * 9;

    for (int ci = 0; ci < Cin; ci += 2) {
        // stage 2 channels of 34x34 input (zero padded)
#pragma unroll
        for (int j = 0; j < 2; j++) {
            const float* src = ip + (size_t)(ci + j) * HW;
            for (int t = tid; t < 34 * 34; t += 256) {
                int iy = t / 34, ix = t - iy * 34;
                int gy = y0 + iy - 1, gx = x0 + ix - 1;
                float v = 0.f;
                if ((unsigned)gy < 128u && (unsigned)gx < 128u) v = src[gy * W_ + gx];
                s_in[j][iy][ix] = v;
            }
        }
        // stage weights: 2 ci x 8 co x 9
        if (tid < 144) {
            int j = tid / 72, rem = tid - j * 72;
            int co = rem / 9, kk = rem - co * 9;
            s_w[j][co][kk] = wp[(size_t)co * Cin * 9 + (ci + j) * 9 + kk];
        }
        __syncthreads();

#pragma unroll
        for (int j = 0; j < 2; j++) {
            float v[4][4];
#pragma unroll
            for (int r = 0; r < 4; r++)
#pragma unroll
                for (int c = 0; c < 4; c++)
                    v[r][c] = s_in[j][2 * ty + r][2 * tx + c];

            u64t pk[4][3];
#pragma unroll
            for (int r = 0; r < 4; r++)
#pragma unroll
                for (int kx = 0; kx < 3; kx++)
                    pk[r][kx] = pk2(v[r][kx], v[r][kx + 1]);

#pragma unroll
            for (int co = 0; co < 8; co++) {
                float4 w0 = *(const float4*)&s_w[j][co][0];
                float4 w1 = *(const float4*)&s_w[j][co][4];
                float4 w2 = *(const float4*)&s_w[j][co][8];
                float wt[9] = {w0.x, w0.y, w0.z, w0.w, w1.x, w1.y, w1.z, w1.w, w2.x};
#pragma unroll
                for (int t9 = 0; t9 < 9; t9++) {
                    u64t wd = pk2(wt[t9], wt[t9]);
                    int ky = t9 / 3, kx = t9 - ky * 3;
                    fma2(acc[co][0], wd, pk[0 + ky][kx]);
                    fma2(acc[co][1], wd, pk[1 + ky][kx]);
                }
            }
        }
        __syncthreads();
    }

    // epilogue: pixels (py+r, px) and (py+r, px+1)
    int px = x0 + 2 * tx, py = y0 + 2 * ty;
    if (OUTNHWC) {
#pragma unroll
        for (int r = 0; r < 2; r++) {
            float2 u[8];
#pragma unroll
            for (int co = 0; co < 8; co++) {
                float bv = bias[co0 + co];
                u[co] = unpk(acc[co][r]);
                u[co].x += bv; u[co].y += bv;
                if (ACT == 1) { u[co].x = gelu_f(u[co].x); u[co].y = gelu_f(u[co].y); }
            }
            int p = (py + r) * W_ + px;
            float* o0 = out + ((size_t)(b * HW) + p) * Cout + co0;
            float* o1 = o0 + Cout;
            *(float4*)(o0)     = make_float4(u[0].x, u[1].x, u[2].x, u[3].x);
            *(float4*)(o0 + 4) = make_float4(u[4].x, u[5].x, u[6].x, u[7].x);
            *(float4*)(o1)     = make_float4(u[0].y, u[1].y, u[2].y, u[3].y);
            *(float4*)(o1 + 4) = make_float4(u[4].y, u[5].y, u[6].y, u[7].y);
        }
    } else {
#pragma unroll
        for (int co = 0; co < 8; co++) {
            float bv = bias[co0 + co];
#pragma unroll
            for (int r = 0; r < 2; r++) {
                float2 u = unpk(acc[co][r]);
                u.x += bv; u.y += bv;
                if (ACT == 1) { u.x = gelu_f(u.x); u.y = gelu_f(u.y); }
                int p = (py + r) * W_ + px;
                *(float2*)(out + ((size_t)(b * Cout) + co0 + co) * HW + p) = u;
            }
        }
    }
}

// ---------------- small direct 3x3 conv (tiny channel counts) ----------------
// ACT: 0 none, 1 gelu, 2 sigmoid, 3 add-to-output-in-place (flow += conv)
template<int CIN, int COUT, int ACT>
__global__ void conv3_small(const float* __restrict__ in, const float* __restrict__ w,
                            const float* __restrict__ bias, float* __restrict__ out)
{
    int idx = blockIdx.x * blockDim.x + threadIdx.x;
    if (idx >= B_ * COUT * HW) return;
    int p  = idx % HW;
    int co = (idx / HW) % COUT;
    int b  = idx / (HW * COUT);
    int y = p >> 7, x = p & 127;

    float acc = bias[co];
    const float* ip = in + (size_t)b * CIN * HW;
    const float* wp = w + (size_t)co * CIN * 9;
#pragma unroll 4
    for (int ci = 0; ci < CIN; ci++) {
#pragma unroll
        for (int ky = 0; ky < 3; ky++) {
            int yy = y + ky - 1;
            if ((unsigned)yy < 128u) {
#pragma unroll
                for (int kx = 0; kx < 3; kx++) {
                    int xx = x + kx - 1;
                    if ((unsigned)xx < 128u)
                        acc += ip[ci * HW + yy * W_ + xx] * wp[ci * 9 + ky * 3 + kx];
                }
            }
        }
    }
    if (ACT == 1) acc = gelu_f(acc);
    if (ACT == 2) acc = 1.0f / (1.0f + expf(-acc));
    if (ACT == 3) acc = out[idx] + acc;
    out[idx] = acc;
}

// ---------------- q/k GEMM (packed f32x2): Out[p,d] = sum_c A[p,c] W[d,c] + b[d] ----------------
__global__ __launch_bounds__(256)
void qk_gemm(const float* __restrict__ A,
             const float* __restrict__ Wq, const float* __restrict__ Bq,
             const float* __restrict__ Wk, const float* __restrict__ Bk,
             float* __restrict__ Qo, float* __restrict__ Ko)
{
    __shared__ float As[8][132];
    __shared__ float Bs[8][132];

    const float* Wm   = blockIdx.y ? Wk : Wq;
    const float* Bias = blockIdx.y ? Bk : Bq;
    float*       Out  = blockIdx.y ? Ko : Qo;

    int m0  = blockIdx.x << 7;
    int tid = threadIdx.x;
    int mr  = (tid >> 4) << 3;
    int nr  = (tid & 15) << 3;

    u64t acc[8][4];
#pragma unroll
    for (int i = 0; i < 8; i++)
#pragma unroll
        for (int m = 0; m < 4; m++) acc[i][m] = 0ull;

    int lr = tid >> 1;
    int lk = (tid & 1) << 2;

    for (int kc = 0; kc < 128; kc += 8) {
        float4 av = *(const float4*)(A  + (size_t)(m0 + lr) * 128 + kc + lk);
        float4 bv = *(const float4*)(Wm + (size_t)lr * 128 + kc + lk);
        As[lk + 0][lr] = av.x; As[lk + 1][lr] = av.y; As[lk + 2][lr] = av.z; As[lk + 3][lr] = av.w;
        Bs[lk + 0][lr] = bv.x; Bs[lk + 1][lr] = bv.y; Bs[lk + 2][lr] = bv.z; Bs[lk + 3][lr] = bv.w;
        __syncthreads();
#pragma unroll
        for (int kk = 0; kk < 8; kk++) {
            float4 a0 = *(const float4*)&As[kk][mr];
            float4 a1 = *(const float4*)&As[kk][mr + 4];
            float4 b0 = *(const float4*)&Bs[kk][nr];
            float4 b1 = *(const float4*)&Bs[kk][nr + 4];
            u64t bp[4] = {pk2(b0.x, b0.y), pk2(b0.z, b0.w), pk2(b1.x, b1.y), pk2(b1.z, b1.w)};
            float a[8] = {a0.x, a0.y, a0.z, a0.w, a1.x, a1.y, a1.z, a1.w};
#pragma unroll
            for (int i = 0; i < 8; i++) {
                u64t ad = pk2(a[i], a[i]);
#pragma unroll
                for (int m = 0; m < 4; m++) fma2(acc[i][m], ad, bp[m]);
            }
        }
        __syncthreads();
    }

    float bn[8];
#pragma unroll
    for (int j = 0; j < 8; j++) bn[j] = Bias[nr + j];
#pragma unroll
    for (int i = 0; i < 8; i++) {
        float2 u0 = unpk(acc[i][0]), u1 = unpk(acc[i][1]);
        float2 u2 = unpk(acc[i][2]), u3 = unpk(acc[i][3]);
        float4 r0 = make_float4(u0.x + bn[0], u0.y + bn[1], u1.x + bn[2], u1.y + bn[3]);
        float4 r1 = make_float4(u2.x + bn[4], u2.y + bn[5], u3.x + bn[6], u3.y + bn[7]);
        *(float4*)(Out + (size_t)(m0 + mr + i) * 128 + nr)     = r0;
        *(float4*)(Out + (size_t)(m0 + mr + i) * 128 + nr + 4) = r1;
    }
}

// ---------------- warp-per-pixel: bilinear warp + diff + L2 normalize + (1 - .) ----------------
__global__ void warp_diff_norm(const float* __restrict__ lf0, const float* __restrict__ lf1,
                               const float* __restrict__ flow, float* __restrict__ feat)
{
    int gw   = (blockIdx.x * blockDim.x + threadIdx.x) >> 5;
    int lane = threadIdx.x & 31;
    int b = gw >> 14;          // gw / HW
    int p = gw & (HW - 1);
    int y = p >> 7, x = p & 127;

    float fx = flow[(size_t)(b * 2) * HW + p];
    float fy = flow[(size_t)(b * 2 + 1) * HW + p];
    float xf = fminf(fmaxf((float)x + fx, 0.f), 127.f);
    float yf = fminf(fmaxf((float)y + fy, 0.f), 127.f);
    float x0f = floorf(xf), y0f = floorf(yf);
    int x0 = (int)x0f, y0 = (int)y0f;
    int x1 = min(x0 + 1, 127), y1 = min(y0 + 1, 127);
    float wx = xf - x0f, wy = yf - y0f;

    const float* base = lf1 + (size_t)b * HW * C_;
    int c4 = lane * 4;
    float4 v00 = *(const float4*)(base + (size_t)(y0 * W_ + x0) * C_ + c4);
    float4 v01 = *(const float4*)(base + (size_t)(y0 * W_ + x1) * C_ + c4);
    float4 v10 = *(const float4*)(base + (size_t)(y1 * W_ + x0) * C_ + c4);
    float4 v11 = *(const float4*)(base + (size_t)(y1 * W_ + x1) * C_ + c4);

    float w00 = (1.f - wx) * (1.f - wy), w01 = wx * (1.f - wy);
    float w10 = (1.f - wx) * wy,         w11 = wx * wy;

    float4 l0 = *(const float4*)(lf0 + (size_t)gw * C_ + c4);
    float dx0 = l0.x - (v00.x * w00 + v01.x * w01 + v10.x * w10 + v11.x * w11);
    float dx1 = l0.y - (v00.y * w00 + v01.y * w01 + v10.y * w10 + v11.y * w11);
    float dx2 = l0.z - (v00.z * w00 + v01.z * w01 + v10.z * w10 + v11.z * w11);
    float dx3 = l0.w - (v00.w * w00 + v01.w * w01 + v10.w * w10 + v11.w * w11);

    float ss = dx0 * dx0 + dx1 * dx1 + dx2 * dx2 + dx3 * dx3;
#pragma unroll
    for (int o = 16; o; o >>= 1) ss += __shfl_xor_sync(0xffffffffu, ss, o);
    float scale = 1.0f / fmaxf(sqrtf(ss), 1e-12f);

    float4 r = make_float4(1.f - dx0 * scale, 1.f - dx1 * scale,
                           1.f - dx2 * scale, 1.f - dx3 * scale);
    *(float4*)(feat + (size_t)gw * C_ + c4) = r;
}

// ---------------- warp-per-pixel: 25-tap local attention on flow ----------------
__global__ void attn_kernel(const float* __restrict__ q, const float* __restrict__ k,
                            const float* __restrict__ flow, float* __restrict__ fi)
{
    int gw   = (blockIdx.x * blockDim.x + threadIdx.x) >> 5;
    int lane = threadIdx.x & 31;
    int b = gw >> 14;
    int p = gw & (HW - 1);
    int y = p >> 7, x = p & 127;

    float4 qv = *(const float4*)(q + (size_t)gw * C_ + lane * 4);

    float myscore = -INFINITY;
#pragma unroll
    for (int t = 0; t < 25; t++) {
        int dy = t / 5 - 2, dx = t % 5 - 2;
        int yy = y + dy, xx = x + dx;
        float s = 0.f;
        if ((unsigned)yy < 128u && (unsigned)xx < 128u) {
            float4 kv = *(const float4*)(k + (size_t)(b * HW + yy * W_ + xx) * C_ + lane * 4);
            s = qv.x * kv.x + qv.y * kv.y + qv.z * kv.z + qv.w * kv.w;
        }
#pragma unroll
        for (int o = 16; o; o >>= 1) s += __shfl_xor_sync(0xffffffffu, s, o);
        if (lane == t) myscore = s * 0.088388347648318447f;  // 1/sqrt(128)
    }
    // softmax across the 25 lanes holding scores
    float m = myscore;
#pragma unroll
    for (int o = 16; o; o >>= 1) m = fmaxf(m, __shfl_xor_sync(0xffffffffu, m, o));
    float e = (lane < 25) ? expf(myscore - m) : 0.f;
    float ssum = e;
#pragma unroll
    for (int o = 16; o; o >>= 1) ssum += __shfl_xor_sync(0xffffffffu, ssum, o);
    float prob = e / ssum;

    float a0 = 0.f, a1 = 0.f;
    if (lane < 25) {
        int dy = lane / 5 - 2, dx = lane % 5 - 2;
        int yy = y + dy, xx = x + dx;
        if ((unsigned)yy < 128u && (unsigned)xx < 128u) {
            a0 = prob * flow[(size_t)(b * 2) * HW + yy * W_ + xx];
            a1 = prob * flow[(size_t)(b * 2 + 1) * HW + yy * W_ + xx];
        }
    }
#pragma unroll
    for (int o = 16; o; o >>= 1) {
        a0 += __shfl_xor_sync(0xffffffffu, a0, o);
        a1 += __shfl_xor_sync(0xffffffffu, a1, o);
    }
    if (lane == 0) {
        fi[(size_t)(b * 2) * HW + p]     = a0;
        fi[(size_t)(b * 2 + 1) * HW + p] = a1;
    }
}

// ---------------- warp feat1 (NHWC) into hcat channels [128,256) (NCHW) ----------------
__global__ void warp_hcat(const float* __restrict__ src, const float* __restrict__ flow,
                          float* __restrict__ hcat)
{
    int gw   = (blockIdx.x * blockDim.x + threadIdx.x) >> 5;
    int lane = threadIdx.x & 31;
    int b = gw >> 14;
    int p = gw & (HW - 1);
    int y = p >> 7, x = p & 127;

    float fx = flow[(size_t)(b * 2) * HW + p];
    float fy = flow[(size_t)(b * 2 + 1) * HW + p];
    float xf = fminf(fmaxf((float)x + fx, 0.f), 127.f);
    float yf = fminf(fmaxf((float)y + fy, 0.f), 127.f);
    float x0f = floorf(xf), y0f = floorf(yf);
    int x0 = (int)x0f, y0 = (int)y0f;
    int x1 = min(x0 + 1, 127), y1 = min(y0 + 1, 127);
    float wx = xf - x0f, wy = yf - y0f;

    const float* base = src + (size_t)b * HW * C_;
    int c4 = lane * 4;
    float4 v00 = *(const float4*)(base + (size_t)(y0 * W_ + x0) * C_ + c4);
    float4 v01 = *(const float4*)(base + (size_t)(y0 * W_ + x1) * C_ + c4);
    float4 v10 = *(const float4*)(base + (size_t)(y1 * W_ + x0) * C_ + c4);
    float4 v11 = *(const float4*)(base + (size_t)(y1 * W_ + x1) * C_ + c4);

    float w00 = (1.f - wx) * (1.f - wy), w01 = wx * (1.f - wy);
    float w10 = (1.f - wx) * wy,         w11 = wx * wy;

    float o0 = v00.x * w00 + v01.x * w01 + v10.x * w10 + v11.x * w11;
    float o1 = v00.y * w00 + v01.y * w01 + v10.y * w10 + v11.y * w11;
    float o2 = v00.z * w00 + v01.z * w01 + v10.z * w10 + v11.z * w11;
    float o3 = v00.w * w00 + v01.w * w01 + v10.w * w10 + v11.w * w11;

    size_t baseo = ((size_t)b * 258 + 128 + c4) * HW + p;
    hcat[baseo]            = o0;
    hcat[baseo + HW]       = o1;
    hcat[baseo + 2 * HW]   = o2;
    hcat[baseo + 3 * HW]   = o3;
}

// ---------------- misc ----------------
__global__ void copy_kernel(const float* __restrict__ in, float* __restrict__ out, int n)
{
    int i = blockIdx.x * blockDim.x + threadIdx.x;
    if (i < n) out[i] = in[i];
}

__global__ void transpose_nhwc(const float* __restrict__ in, float* __restrict__ out)
{
    int idx = blockIdx.x * blockDim.x + threadIdx.x;
    if (idx >= B_ * C_ * HW) return;
    int p = idx & (HW - 1);
    int c = (idx >> 14) & 127;
    int b = idx >> 21;
    out[((size_t)(b * HW) + p) * C_ + c] = in[idx];
}

__global__ void hcat_fill(const float* __restrict__ feat0, const float* __restrict__ flow,
                          float* __restrict__ hcat)
{
    int idx = blockIdx.x * blockDim.x + threadIdx.x;
    if (idx >= B_ * 130 * HW) return;
    int p = idx % HW;
    int c = (idx / HW) % 130;
    int b = idx / (130 * HW);
    if (c < 128) {
        hcat[((size_t)b * 258 + c) * HW + p] = feat0[((size_t)b * 128 + c) * HW + p];
    } else {
        int f = c - 128;
        hcat[((size_t)b * 258 + 256 + f) * HW + p] = flow[((size_t)b * 2 + f) * HW + p];
    }
}

// ---------------- launch ----------------
extern "C" void kernel_launch(void* const* d_in, const int* in_sizes, int n_in,
                              void* d_out, int out_size)
{
    const float* feat0     = (const float*)d_in[0];
    const float* feat1     = (const float*)d_in[1];
    const float* flow_init = (const float*)d_in[2];
    const float* lc_w1 = (const float*)d_in[3];
    const float* lc_b1 = (const float*)d_in[4];
    const float* lc_w2 = (const float*)d_in[5];
    const float* lc_b2 = (const float*)d_in[6];
    const float* qw    = (const float*)d_in[7];
    const float* qb    = (const float*)d_in[8];
    const float* kw    = (const float*)d_in[9];
    const float* kb    = (const float*)d_in[10];
    const float* fr_w1 = (const float*)d_in[11];
    const float* fr_b1 = (const float*)d_in[12];
    const float* fr_w2 = (const float*)d_in[13];
    const float* fr_b2 = (const float*)d_in[14];
    const float* fr_w3 = (const float*)d_in[15];
    const float* fr_b3 = (const float*)d_in[16];
    const float* cf_w1 = (const float*)d_in[17];
    const float* cf_b1 = (const float*)d_in[18];
    const float* cf_w2 = (const float*)d_in[19];
    const float* cf_b2 = (const float*)d_in[20];
    const float* cf_w3 = (const float*)d_in[21];
    const float* cf_b3 = (const float*)d_in[22];
    float* out = (float*)d_out;

    float *p_tmp, *p_lf0, *p_lf1, *p_f1t, *p_feat, *p_q, *p_k;
    float *p_fi, *p_d1, *p_d2, *p_flow, *p_hcat, *p_h1, *p_h2;
    cudaGetSymbolAddress((void**)&p_tmp,  g_tmp);
    cudaGetSymbolAddress((void**)&p_lf0,  g_lf0);
    cudaGetSymbolAddress((void**)&p_lf1,  g_lf1);
    cudaGetSymbolAddress((void**)&p_f1t,  g_f1t);
    cudaGetSymbolAddress((void**)&p_feat, g_feat);
    cudaGetSymbolAddress((void**)&p_q,    g_q);
    cudaGetSymbolAddress((void**)&p_k,    g_k);
    cudaGetSymbolAddress((void**)&p_fi,   g_fi);
    cudaGetSymbolAddress((void**)&p_d1,   g_d1);
    cudaGetSymbolAddress((void**)&p_d2,   g_d2);
    cudaGetSymbolAddress((void**)&p_flow, g_flow);
    cudaGetSymbolAddress((void**)&p_hcat, g_hcat);
    cudaGetSymbolAddress((void**)&p_h1,   g_h1);
    cudaGetSymbolAddress((void**)&p_h2,   g_h2);

    dim3 g128(4, 4, B_ * 16);   // Cout=128 -> 16 groups of 8
    dim3 g64 (4, 4, B_ * 8);    // Cout=64  -> 8 groups of 8

    // local_conv chain (hoisted): lf0, lf1 in NHWC
    conv3_v2<1, 0><<<g128, 256>>>(feat0, lc_w1, lc_b1, p_tmp, 128, 128);
    conv3_v2<0, 1><<<g128, 256>>>(p_tmp, lc_w2, lc_b2, p_lf0, 128, 128);
    conv3_v2<1, 0><<<g128, 256>>>(feat1, lc_w1, lc_b1, p_tmp, 128, 128);
    conv3_v2<0, 1><<<g128, 256>>>(p_tmp, lc_w2, lc_b2, p_lf1, 128, 128);
    transpose_nhwc<<<(B_ * C_ * HW) / 256, 256>>>(feat1, p_f1t);
    copy_kernel<<<(B_ * 2 * HW) / 256, 256>>>(flow_init, p_flow, B_ * 2 * HW);

    for (int it = 0; it < ITERS; it++) {
        warp_diff_norm<<<(B_ * HW) / 4, 128>>>(p_lf0, p_lf1, p_flow, p_feat);
        qk_gemm<<<dim3((B_ * HW) / 128, 2), 256>>>(p_feat, qw, qb, kw, kb, p_q, p_k);
        attn_kernel<<<(B_ * HW) / 4, 128>>>(p_q, p_k, p_flow, p_fi);
        conv3_small<2, 16, 1><<<(B_ * 16 * HW + 255) / 256, 256>>>(p_fi, fr_w1, fr_b1, p_d1);
        conv3_small<16, 16, 1><<<(B_ * 16 * HW + 255) / 256, 256>>>(p_d1, fr_w2, fr_b2, p_d2);
        conv3_small<16, 2, 3><<<(B_ * 2 * HW + 255) / 256, 256>>>(p_d2, fr_w3, fr_b3, p_flow);
    }

    // confidence head
    hcat_fill<<<(B_ * 130 * HW + 255) / 256, 256>>>(feat0, p_flow, p_hcat);
    warp_hcat<<<(B_ * HW) / 4, 128>>>(p_f1t, p_flow, p_hcat);
    conv3_v2<1, 0><<<g128, 256>>>(p_hcat, cf_w1, cf_b1, p_h1, 258, 128);
    conv3_v2<1, 0><<<g64,  256>>>(p_h1,  cf_w2, cf_b2, p_h2, 128, 64);
    conv3_small<64, 1, 2><<<(B_ * HW + 255) / 256, 256>>>(p_h2, cf_w3, cf_b3, out + B_ * 2 * HW);

    // outputs: flow then conf
    copy_kernel<<<(B_ * 2 * HW) / 256, 256>>>(p_flow, out, B_ * 2 * HW);
}

// round 6
// speedup vs baseline: 1.6070x; 1.5279x over previous
#include <cuda_runtime.h>
#include <math.h>

#define HW   16384
#define W_   128
#define H_   128
#define C_   128
#define B_   2
#define ITERS 10
#define HCATC 264   // 258 padded to multiple of 8

// ---------------- scratch (static device globals; no allocation) ----------------
__device__ float g_tmp [B_*HW*C_];     // NHWC conv intermediate
__device__ float g_lf0 [B_*HW*C_];     // NHWC
__device__ float g_lf1 [B_*HW*C_];     // NHWC
__device__ float g_f1t [B_*HW*C_];     // feat1 NHWC
__device__ float g_feat[B_*HW*C_];     // NHWC
__device__ float g_q   [B_*HW*C_];     // NHWC
__device__ float g_k   [B_*HW*C_];     // NHWC
__device__ float g_fi  [B_*2*HW];      // NCHW
__device__ float g_d1  [B_*16*HW];
__device__ float g_d2  [B_*16*HW];
__device__ float g_flow[B_*2*HW];      // NCHW
__device__ float g_hcat[B_*HW*HCATC]; // NHWC padded
__device__ float g_h1  [B_*HW*C_];     // NHWC
__device__ float g_h2  [B_*HW*64];     // NHWC
// repacked tf32-split weights: [tap][ci_pad][co]
__device__ float g_wAhi[9*HCATC*C_];
__device__ float g_wAlo[9*HCATC*C_];
__device__ float g_wBhi[9*C_*C_];
__device__ float g_wBlo[9*C_*C_];

__device__ __forceinline__ float gelu_f(float x) {
    return 0.5f * x * (1.0f + erff(x * 0.70710678118654752440f));
}

// ---------------- tf32 helpers ----------------
__device__ __forceinline__ unsigned cvt_tf32(float x) {
    unsigned r; asm("cvt.rna.tf32.f32 %0, %1;" : "=r"(r) : "f"(x)); return r;
}
__device__ __forceinline__ void mma_tf32(float* c, const unsigned* a, const unsigned* b) {
    asm volatile(
        "mma.sync.aligned.m16n8k8.row.col.f32.tf32.tf32.f32 "
        "{%0,%1,%2,%3}, {%4,%5,%6,%7}, {%8,%9}, {%0,%1,%2,%3};"
        : "+f"(c[0]), "+f"(c[1]), "+f"(c[2]), "+f"(c[3])
        : "r"(a[0]), "r"(a[1]), "r"(a[2]), "r"(a[3]), "r"(b[0]), "r"(b[1]));
}

// ---------------- weight repack + tf32 hi/lo split ----------------
// OIHW w[co][ci][tap] -> Whi/Wlo[((tap*Cin_pad)+ci)*Cout + co], zero-pad ci>=Cin
__global__ void repack_w(const float* __restrict__ w, float* __restrict__ whi,
                         float* __restrict__ wlo, int Cin, int Cin_pad, int Cout, int total)
{
    int idx = blockIdx.x * blockDim.x + threadIdx.x;
    if (idx >= total) return;
    int co = idx % Cout;
    int r  = idx / Cout;
    int ci = r % Cin_pad;
    int tap = r / Cin_pad;
    float v = (ci < Cin) ? w[((size_t)co * Cin + ci) * 9 + tap] : 0.f;
    float h = __uint_as_float(cvt_tf32(v));
    float l = __uint_as_float(cvt_tf32(v - h));
    whi[idx] = h;
    wlo[idx] = l;
}

// ---------------- tensor-core 3x3 conv (implicit GEMM, tf32 3x split) ----------------
// CTA: 16x8 pixel tile (M=128), N=64 output channels. 256 threads = 8 warps (4M x 2N).
// ACT: 0 none, 1 gelu. INNHWC: input layout.
#define SIN(py_, px_, k_) s_in[((py_)*18 + (px_))*9 + (k_)]
template<int ACT, int INNHWC>
__global__ __launch_bounds__(256)
void conv3_mma(const float* __restrict__ in, const float* __restrict__ whi,
               const float* __restrict__ wlo, const float* __restrict__ bias,
               float* __restrict__ out, int Cin_pad, int inC, int CoutT)
{
    __shared__ float s_in[10*18*9];   // halo 18x10 pixels x 8 ci (stride 9)
    __shared__ float s_bh[8*68];      // weight slab hi: [k][n] stride 68
    __shared__ float s_bl[8*68];

    int b   = blockIdx.z;
    int co0 = blockIdx.y << 6;
    int x0  = (blockIdx.x & 7) << 4;
    int y0  = (blockIdx.x >> 3) << 3;
    int tid = threadIdx.x;
    int lane = tid & 31, warp = tid >> 5;
    int warpM = warp >> 1, warpN = warp & 1;
    int qr = lane >> 2, qc = lane & 3;

    float c[2][4][4];
#pragma unroll
    for (int mt = 0; mt < 2; mt++)
#pragma unroll
        for (int nt = 0; nt < 4; nt++)
#pragma unroll
            for (int i = 0; i < 4; i++) c[mt][nt][i] = 0.f;

    int nchunk = Cin_pad >> 3;
    for (int ch = 0; ch < nchunk; ch++) {
        int ci0 = ch << 3;
        __syncthreads();   // previous tap's mma done: safe to overwrite s_in / slabs

        // ---- stage input halo tile (8 channels) ----
        if (INNHWC) {
            for (int t = tid; t < 360; t += 256) {
                int pxi = t >> 1, half = t & 1;
                int iy = pxi / 18, ix = pxi - iy * 18;
                int gy = y0 - 1 + iy, gx = x0 - 1 + ix;
                float4 v = make_float4(0.f, 0.f, 0.f, 0.f);
                if ((unsigned)gy < 128u && (unsigned)gx < 128u)
                    v = *(const float4*)(in + ((size_t)(b * HW) + gy * W_ + gx) * inC + ci0 + half * 4);
                int base = (iy * 18 + ix) * 9 + half * 4;
                s_in[base + 0] = v.x; s_in[base + 1] = v.y;
                s_in[base + 2] = v.z; s_in[base + 3] = v.w;
            }
        } else {
            for (int t = tid; t < 1440; t += 256) {
                int ix = t % 18, r = t / 18;
                int iy = r % 10, cc = r / 10;
                int gy = y0 - 1 + iy, gx = x0 - 1 + ix;
                float v = 0.f;
                if ((unsigned)gy < 128u && (unsigned)gx < 128u)
                    v = in[((size_t)(b * inC) + ci0 + cc) * HW + gy * W_ + gx];
                s_in[(iy * 18 + ix) * 9 + cc] = v;
            }
        }

        for (int tap = 0; tap < 9; tap++) {
            if (tap > 0) __syncthreads();  // previous tap's mma done before slab overwrite
            // ---- stage weight slab (8 ci x 64 co, hi+lo) ----
            {
                const float* bh = whi + ((size_t)tap * Cin_pad + ci0) * CoutT + co0;
                const float* bl = wlo + ((size_t)tap * Cin_pad + ci0) * CoutT + co0;
                for (int t = tid; t < 512; t += 256) {
                    int n = t & 63, kk = t >> 6;
                    s_bh[kk * 68 + n] = bh[(size_t)kk * CoutT + n];
                    s_bl[kk * 68 + n] = bl[(size_t)kk * CoutT + n];
                }
            }
            __syncthreads();

            int ky = tap / 3, kx = tap - ky * 3;

            // ---- A fragments (hi/lo split in registers) ----
            unsigned ahi[2][4], alo[2][4];
#pragma unroll
            for (int mt = 0; mt < 2; mt++) {
                int r0 = warpM * 32 + mt * 16 + qr;
                int r1 = r0 + 8;
                int p0y = (r0 >> 4) + ky, p0x = (r0 & 15) + kx;
                int p1y = (r1 >> 4) + ky, p1x = (r1 & 15) + kx;
                float a0 = SIN(p0y, p0x, qc);
                float a1 = SIN(p1y, p1x, qc);
                float a2 = SIN(p0y, p0x, qc + 4);
                float a3 = SIN(p1y, p1x, qc + 4);
                ahi[mt][0] = cvt_tf32(a0); alo[mt][0] = cvt_tf32(a0 - __uint_as_float(ahi[mt][0]));
                ahi[mt][1] = cvt_tf32(a1); alo[mt][1] = cvt_tf32(a1 - __uint_as_float(ahi[mt][1]));
                ahi[mt][2] = cvt_tf32(a2); alo[mt][2] = cvt_tf32(a2 - __uint_as_float(ahi[mt][2]));
                ahi[mt][3] = cvt_tf32(a3); alo[mt][3] = cvt_tf32(a3 - __uint_as_float(ahi[mt][3]));
            }
            // ---- B fragments + mma ----
#pragma unroll
            for (int nt = 0; nt < 4; nt++) {
                int n = warpN * 32 + nt * 8 + qr;
                unsigned bh[2], bl[2];
                bh[0] = __float_as_uint(s_bh[qc * 68 + n]);
                bh[1] = __float_as_uint(s_bh[(qc + 4) * 68 + n]);
                bl[0] = __float_as_uint(s_bl[qc * 68 + n]);
                bl[1] = __float_as_uint(s_bl[(qc + 4) * 68 + n]);
#pragma unroll
                for (int mt = 0; mt < 2; mt++) {
                    mma_tf32(c[mt][nt], ahi[mt], bh);
                    mma_tf32(c[mt][nt], ahi[mt], bl);
                    mma_tf32(c[mt][nt], alo[mt], bh);
                }
            }
        }
    }

    // ---- epilogue: bias + act + NHWC store (float2 per c-pair) ----
#pragma unroll
    for (int nt = 0; nt < 4; nt++) {
        int col = co0 + warpN * 32 + nt * 8 + qc * 2;
        float b0 = bias[col], b1 = bias[col + 1];
#pragma unroll
        for (int mt = 0; mt < 2; mt++) {
            int r0 = warpM * 32 + mt * 16 + qr;
            int r1 = r0 + 8;
            int P0 = (y0 + (r0 >> 4)) * W_ + x0 + (r0 & 15);
            int P1 = (y0 + (r1 >> 4)) * W_ + x0 + (r1 & 15);
            float v0 = c[mt][nt][0] + b0, v1 = c[mt][nt][1] + b1;
            float v2 = c[mt][nt][2] + b0, v3 = c[mt][nt][3] + b1;
            if (ACT == 1) { v0 = gelu_f(v0); v1 = gelu_f(v1); v2 = gelu_f(v2); v3 = gelu_f(v3); }
            *(float2*)(out + ((size_t)(b * HW) + P0) * CoutT + col) = make_float2(v0, v1);
            *(float2*)(out + ((size_t)(b * HW) + P1) * CoutT + col) = make_float2(v2, v3);
        }
    }
}

// ---------------- small direct 3x3 conv (tiny channel counts, NCHW) ----------------
template<int CIN, int COUT, int ACT>
__global__ void conv3_small(const float* __restrict__ in, const float* __restrict__ w,
                            const float* __restrict__ bias, float* __restrict__ out)
{
    int idx = blockIdx.x * blockDim.x + threadIdx.x;
    if (idx >= B_ * COUT * HW) return;
    int p  = idx % HW;
    int co = (idx / HW) % COUT;
    int b  = idx / (HW * COUT);
    int y = p >> 7, x = p & 127;

    float acc = bias[co];
    const float* ip = in + (size_t)b * CIN * HW;
    const float* wp = w + (size_t)co * CIN * 9;
#pragma unroll 4
    for (int ci = 0; ci < CIN; ci++) {
#pragma unroll
        for (int ky = 0; ky < 3; ky++) {
            int yy = y + ky - 1;
            if ((unsigned)yy < 128u) {
#pragma unroll
                for (int kx = 0; kx < 3; kx++) {
                    int xx = x + kx - 1;
                    if ((unsigned)xx < 128u)
                        acc += ip[ci * HW + yy * W_ + xx] * wp[ci * 9 + ky * 3 + kx];
                }
            }
        }
    }
    if (ACT == 1) acc = gelu_f(acc);
    if (ACT == 3) acc = out[idx] + acc;
    out[idx] = acc;
}

// ---------------- final conv 64->1 + sigmoid, NHWC input, warp per pixel ----------------
__global__ void conv_final_nhwc(const float* __restrict__ h2, const float* __restrict__ w,
                                const float* __restrict__ bias, float* __restrict__ outc)
{
    int gw   = (blockIdx.x * blockDim.x + threadIdx.x) >> 5;
    int lane = threadIdx.x & 31;
    int b = gw >> 14;
    int p = gw & (HW - 1);
    int y = p >> 7, x = p & 127;
    int c0 = lane * 2;

    float acc = 0.f;
#pragma unroll
    for (int tap = 0; tap < 9; tap++) {
        int ky = tap / 3, kx = tap - ky * 3;
        int yy = y + ky - 1, xx = x + kx - 1;
        if ((unsigned)yy < 128u && (unsigned)xx < 128u) {
            float2 v = *(const float2*)(h2 + ((size_t)(b * HW) + yy * W_ + xx) * 64 + c0);
            acc += v.x * w[c0 * 9 + tap] + v.y * w[(c0 + 1) * 9 + tap];
        }
    }
#pragma unroll
    for (int o = 16; o; o >>= 1) acc += __shfl_xor_sync(0xffffffffu, acc, o);
    if (lane == 0)
        outc[b * HW + p] = 1.0f / (1.0f + expf(-(acc + bias[0])));
}

// ---------------- q/k GEMM (packed f32x2) ----------------
typedef unsigned long long u64t;
__device__ __forceinline__ u64t pk2(float lo, float hi) {
    u64t r; asm("mov.b64 %0, {%1,%2};" : "=l"(r) : "f"(lo), "f"(hi)); return r;
}
__device__ __forceinline__ void fma2(u64t& d, u64t a, u64t b) {
    asm("fma.rn.f32x2 %0, %1, %2, %0;" : "+l"(d) : "l"(a), "l"(b));
}
__device__ __forceinline__ float2 unpk(u64t v) {
    float2 r; asm("mov.b64 {%0,%1}, %2;" : "=f"(r.x), "=f"(r.y) : "l"(v)); return r;
}

__global__ __launch_bounds__(256)
void qk_gemm(const float* __restrict__ A,
             const float* __restrict__ Wq, const float* __restrict__ Bq,
             const float* __restrict__ Wk, const float* __restrict__ Bk,
             float* __restrict__ Qo, float* __restrict__ Ko)
{
    __shared__ float As[8][132];
    __shared__ float Bs[8][132];

    const float* Wm   = blockIdx.y ? Wk : Wq;
    const float* Bias = blockIdx.y ? Bk : Bq;
    float*       Out  = blockIdx.y ? Ko : Qo;

    int m0  = blockIdx.x << 7;
    int tid = threadIdx.x;
    int mr  = (tid >> 4) << 3;
    int nr  = (tid & 15) << 3;

    u64t acc[8][4];
#pragma unroll
    for (int i = 0; i < 8; i++)
#pragma unroll
        for (int m = 0; m < 4; m++) acc[i][m] = 0ull;

    int lr = tid >> 1;
    int lk = (tid & 1) << 2;

    for (int kc = 0; kc < 128; kc += 8) {
        float4 av = *(const float4*)(A  + (size_t)(m0 + lr) * 128 + kc + lk);
        float4 bv = *(const float4*)(Wm + (size_t)lr * 128 + kc + lk);
        As[lk + 0][lr] = av.x; As[lk + 1][lr] = av.y; As[lk + 2][lr] = av.z; As[lk + 3][lr] = av.w;
        Bs[lk + 0][lr] = bv.x; Bs[lk + 1][lr] = bv.y; Bs[lk + 2][lr] = bv.z; Bs[lk + 3][lr] = bv.w;
        __syncthreads();
#pragma unroll
        for (int kk = 0; kk < 8; kk++) {
            float4 a0 = *(const float4*)&As[kk][mr];
            float4 a1 = *(const float4*)&As[kk][mr + 4];
            float4 b0 = *(const float4*)&Bs[kk][nr];
            float4 b1 = *(const float4*)&Bs[kk][nr + 4];
            u64t bp[4] = {pk2(b0.x, b0.y), pk2(b0.z, b0.w), pk2(b1.x, b1.y), pk2(b1.z, b1.w)};
            float a[8] = {a0.x, a0.y, a0.z, a0.w, a1.x, a1.y, a1.z, a1.w};
#pragma unroll
            for (int i = 0; i < 8; i++) {
                u64t ad = pk2(a[i], a[i]);
#pragma unroll
                for (int m = 0; m < 4; m++) fma2(acc[i][m], ad, bp[m]);
            }
        }
        __syncthreads();
    }

    float bn[8];
#pragma unroll
    for (int j = 0; j < 8; j++) bn[j] = Bias[nr + j];
#pragma unroll
    for (int i = 0; i < 8; i++) {
        float2 u0 = unpk(acc[i][0]), u1 = unpk(acc[i][1]);
        float2 u2 = unpk(acc[i][2]), u3 = unpk(acc[i][3]);
        float4 r0 = make_float4(u0.x + bn[0], u0.y + bn[1], u1.x + bn[2], u1.y + bn[3]);
        float4 r1 = make_float4(u2.x + bn[4], u2.y + bn[5], u3.x + bn[6], u3.y + bn[7]);
        *(float4*)(Out + (size_t)(m0 + mr + i) * 128 + nr)     = r0;
        *(float4*)(Out + (size_t)(m0 + mr + i) * 128 + nr + 4) = r1;
    }
}

// ---------------- warp-per-pixel: bilinear warp + diff + L2 normalize + (1 - .) ----------------
__global__ void warp_diff_norm(const float* __restrict__ lf0, const float* __restrict__ lf1,
                               const float* __restrict__ flow, float* __restrict__ feat)
{
    int gw   = (blockIdx.x * blockDim.x + threadIdx.x) >> 5;
    int lane = threadIdx.x & 31;
    int b = gw >> 14;
    int p = gw & (HW - 1);
    int y = p >> 7, x = p & 127;

    float fx = flow[(size_t)(b * 2) * HW + p];
    float fy = flow[(size_t)(b * 2 + 1) * HW + p];
    float xf = fminf(fmaxf((float)x + fx, 0.f), 127.f);
    float yf = fminf(fmaxf((float)y + fy, 0.f), 127.f);
    float x0f = floorf(xf), y0f = floorf(yf);
    int x0 = (int)x0f, y0 = (int)y0f;
    int x1 = min(x0 + 1, 127), y1 = min(y0 + 1, 127);
    float wx = xf - x0f, wy = yf - y0f;

    const float* base = lf1 + (size_t)b * HW * C_;
    int c4 = lane * 4;
    float4 v00 = *(const float4*)(base + (size_t)(y0 * W_ + x0) * C_ + c4);
    float4 v01 = *(const float4*)(base + (size_t)(y0 * W_ + x1) * C_ + c4);
    float4 v10 = *(const float4*)(base + (size_t)(y1 * W_ + x0) * C_ + c4);
    float4 v11 = *(const float4*)(base + (size_t)(y1 * W_ + x1) * C_ + c4);

    float w00 = (1.f - wx) * (1.f - wy), w01 = wx * (1.f - wy);
    float w10 = (1.f - wx) * wy,         w11 = wx * wy;

    float4 l0 = *(const float4*)(lf0 + (size_t)gw * C_ + c4);
    float dx0 = l0.x - (v00.x * w00 + v01.x * w01 + v10.x * w10 + v11.x * w11);
    float dx1 = l0.y - (v00.y * w00 + v01.y * w01 + v10.y * w10 + v11.y * w11);
    float dx2 = l0.z - (v00.z * w00 + v01.z * w01 + v10.z * w10 + v11.z * w11);
    float dx3 = l0.w - (v00.w * w00 + v01.w * w01 + v10.w * w10 + v11.w * w11);

    float ss = dx0 * dx0 + dx1 * dx1 + dx2 * dx2 + dx3 * dx3;
#pragma unroll
    for (int o = 16; o; o >>= 1) ss += __shfl_xor_sync(0xffffffffu, ss, o);
    float scale = 1.0f / fmaxf(sqrtf(ss), 1e-12f);

    float4 r = make_float4(1.f - dx0 * scale, 1.f - dx1 * scale,
                           1.f - dx2 * scale, 1.f - dx3 * scale);
    *(float4*)(feat + (size_t)gw * C_ + c4) = r;
}

// ---------------- warp-per-pixel: 25-tap local attention on flow ----------------
__global__ void attn_kernel(const float* __restrict__ q, const float* __restrict__ k,
                            const float* __restrict__ flow, float* __restrict__ fi)
{
    int gw   = (blockIdx.x * blockDim.x + threadIdx.x) >> 5;
    int lane = threadIdx.x & 31;
    int b = gw >> 14;
    int p = gw & (HW - 1);
    int y = p >> 7, x = p & 127;

    float4 qv = *(const float4*)(q + (size_t)gw * C_ + lane * 4);

    float myscore = -INFINITY;
#pragma unroll
    for (int t = 0; t < 25; t++) {
        int dy = t / 5 - 2, dx = t % 5 - 2;
        int yy = y + dy, xx = x + dx;
        float s = 0.f;
        if ((unsigned)yy < 128u && (unsigned)xx < 128u) {
            float4 kv = *(const float4*)(k + (size_t)(b * HW + yy * W_ + xx) * C_ + lane * 4);
            s = qv.x * kv.x + qv.y * kv.y + qv.z * kv.z + qv.w * kv.w;
        }
#pragma unroll
        for (int o = 16; o; o >>= 1) s += __shfl_xor_sync(0xffffffffu, s, o);
        if (lane == t) myscore = s * 0.088388347648318447f;
    }
    float m = myscore;
#pragma unroll
    for (int o = 16; o; o >>= 1) m = fmaxf(m, __shfl_xor_sync(0xffffffffu, m, o));
    float e = (lane < 25) ? expf(myscore - m) : 0.f;
    float ssum = e;
#pragma unroll
    for (int o = 16; o; o >>= 1) ssum += __shfl_xor_sync(0xffffffffu, ssum, o);
    float prob = e / ssum;

    float a0 = 0.f, a1 = 0.f;
    if (lane < 25) {
        int dy = lane / 5 - 2, dx = lane % 5 - 2;
        int yy = y + dy, xx = x + dx;
        if ((unsigned)yy < 128u && (unsigned)xx < 128u) {
            a0 = prob * flow[(size_t)(b * 2) * HW + yy * W_ + xx];
            a1 = prob * flow[(size_t)(b * 2 + 1) * HW + yy * W_ + xx];
        }
    }
#pragma unroll
    for (int o = 16; o; o >>= 1) {
        a0 += __shfl_xor_sync(0xffffffffu, a0, o);
        a1 += __shfl_xor_sync(0xffffffffu, a1, o);
    }
    if (lane == 0) {
        fi[(size_t)(b * 2) * HW + p]     = a0;
        fi[(size_t)(b * 2 + 1) * HW + p] = a1;
    }
}

// ---------------- warp feat1 (NHWC) -> hcat NHWC channels [128,256) ----------------
__global__ void warp_hcat_nhwc(const float* __restrict__ src, const float* __restrict__ flow,
                               float* __restrict__ hcat)
{
    int gw   = (blockIdx.x * blockDim.x + threadIdx.x) >> 5;
    int lane = threadIdx.x & 31;
    int b = gw >> 14;
    int p = gw & (HW - 1);
    int y = p >> 7, x = p & 127;

    float fx = flow[(size_t)(b * 2) * HW + p];
    float fy = flow[(size_t)(b * 2 + 1) * HW + p];
    float xf = fminf(fmaxf((float)x + fx, 0.f), 127.f);
    float yf = fminf(fmaxf((float)y + fy, 0.f), 127.f);
    float x0f = floorf(xf), y0f = floorf(yf);
    int x0 = (int)x0f, y0 = (int)y0f;
    int x1 = min(x0 + 1, 127), y1 = min(y0 + 1, 127);
    float wx = xf - x0f, wy = yf - y0f;

    const float* base = src + (size_t)b * HW * C_;
    int c4 = lane * 4;
    float4 v00 = *(const float4*)(base + (size_t)(y0 * W_ + x0) * C_ + c4);
    float4 v01 = *(const float4*)(base + (size_t)(y0 * W_ + x1) * C_ + c4);
    float4 v10 = *(const float4*)(base + (size_t)(y1 * W_ + x0) * C_ + c4);
    float4 v11 = *(const float4*)(base + (size_t)(y1 * W_ + x1) * C_ + c4);

    float w00 = (1.f - wx) * (1.f - wy), w01 = wx * (1.f - wy);
    float w10 = (1.f - wx) * wy,         w11 = wx * wy;

    float4 o;
    o.x = v00.x * w00 + v01.x * w01 + v10.x * w10 + v11.x * w11;
    o.y = v00.y * w00 + v01.y * w01 + v10.y * w10 + v11.y * w11;
    o.z = v00.z * w00 + v01.z * w01 + v10.z * w10 + v11.z * w11;
    o.w = v00.w * w00 + v01.w * w01 + v10.w * w10 + v11.w * w11;

    *(float4*)(hcat + ((size_t)(b * HW) + p) * HCATC + 128 + c4) = o;
}

// ---------------- misc ----------------
__global__ void copy_kernel(const float* __restrict__ in, float* __restrict__ out, int n)
{
    int i = blockIdx.x * blockDim.x + threadIdx.x;
    if (i < n) out[i] = in[i];
}

__global__ void transpose_nhwc(const float* __restrict__ in, float* __restrict__ out)
{
    int idx = blockIdx.x * blockDim.x + threadIdx.x;
    if (idx >= B_ * C_ * HW) return;
    int p = idx & (HW - 1);
    int c = (idx >> 14) & 127;
    int b = idx >> 21;
    out[((size_t)(b * HW) + p) * C_ + c] = in[idx];
}

// feat0 NCHW -> hcat NHWC channels [0,128), tiled transpose
__global__ void feat0_to_hcat(const float* __restrict__ feat0, float* __restrict__ hcat)
{
    __shared__ float tile[32][33];
    int p0 = blockIdx.x << 5, c0 = blockIdx.y << 5, b = blockIdx.z;
    for (int i = threadIdx.y; i < 32; i += 8)
        tile[i][threadIdx.x] = feat0[((size_t)(b * 128) + c0 + i) * HW + p0 + threadIdx.x];
    __syncthreads();
    for (int i = threadIdx.y; i < 32; i += 8)
        hcat[((size_t)(b * HW) + p0 + i) * HCATC + c0 + threadIdx.x] = tile[threadIdx.x][i];
}

// flow -> hcat channels [256,258); zero-pad [258,264)
__global__ void hcat_tail(const float* __restrict__ flow, float* __restrict__ hcat)
{
    int idx = blockIdx.x * blockDim.x + threadIdx.x;
    if (idx >= B_ * HW * 8) return;
    int c = idx & 7;
    int p = (idx >> 3) & (HW - 1);
    int b = idx >> 17;
    float v = (c < 2) ? flow[((size_t)(b * 2) + c) * HW + p] : 0.f;
    hcat[((size_t)(b * HW) + p) * HCATC + 256 + c] = v;
}

// ---------------- launch ----------------
extern "C" void kernel_launch(void* const* d_in, const int* in_sizes, int n_in,
                              void* d_out, int out_size)
{
    const float* feat0     = (const float*)d_in[0];
    const float* feat1     = (const float*)d_in[1];
    const float* flow_init = (const float*)d_in[2];
    const float* lc_w1 = (const float*)d_in[3];
    const float* lc_b1 = (const float*)d_in[4];
    const float* lc_w2 = (const float*)d_in[5];
    const float* lc_b2 = (const float*)d_in[6];
    const float* qw    = (const float*)d_in[7];
    const float* qb    = (const float*)d_in[8];
    const float* kw    = (const float*)d_in[9];
    const float* kb    = (const float*)d_in[10];
    const float* fr_w1 = (const float*)d_in[11];
    const float* fr_b1 = (const float*)d_in[12];
    const float* fr_w2 = (const float*)d_in[13];
    const float* fr_b2 = (const float*)d_in[14];
    const float* fr_w3 = (const float*)d_in[15];
    const float* fr_b3 = (const float*)d_in[16];
    const float* cf_w1 = (const float*)d_in[17];
    const float* cf_b1 = (const float*)d_in[18];
    const float* cf_w2 = (const float*)d_in[19];
    const float* cf_b2 = (const float*)d_in[20];
    const float* cf_w3 = (const float*)d_in[21];
    const float* cf_b3 = (const float*)d_in[22];
    float* out = (float*)d_out;

    float *p_tmp, *p_lf0, *p_lf1, *p_f1t, *p_feat, *p_q, *p_k;
    float *p_fi, *p_d1, *p_d2, *p_flow, *p_hcat, *p_h1, *p_h2;
    float *p_wAh, *p_wAl, *p_wBh, *p_wBl;
    cudaGetSymbolAddress((void**)&p_tmp,  g_tmp);
    cudaGetSymbolAddress((void**)&p_lf0,  g_lf0);
    cudaGetSymbolAddress((void**)&p_lf1,  g_lf1);
    cudaGetSymbolAddress((void**)&p_f1t,  g_f1t);
    cudaGetSymbolAddress((void**)&p_feat, g_feat);
    cudaGetSymbolAddress((void**)&p_q,    g_q);
    cudaGetSymbolAddress((void**)&p_k,    g_k);
    cudaGetSymbolAddress((void**)&p_fi,   g_fi);
    cudaGetSymbolAddress((void**)&p_d1,   g_d1);
    cudaGetSymbolAddress((void**)&p_d2,   g_d2);
    cudaGetSymbolAddress((void**)&p_flow, g_flow);
    cudaGetSymbolAddress((void**)&p_hcat, g_hcat);
    cudaGetSymbolAddress((void**)&p_h1,   g_h1);
    cudaGetSymbolAddress((void**)&p_h2,   g_h2);
    cudaGetSymbolAddress((void**)&p_wAh,  g_wAhi);
    cudaGetSymbolAddress((void**)&p_wAl,  g_wAlo);
    cudaGetSymbolAddress((void**)&p_wBh,  g_wBhi);
    cudaGetSymbolAddress((void**)&p_wBl,  g_wBlo);

    // repack local_conv weights
    int totA = 9 * 128 * 128;
    repack_w<<<(totA + 255) / 256, 256>>>(lc_w1, p_wAh, p_wAl, 128, 128, 128, totA);
    repack_w<<<(totA + 255) / 256, 256>>>(lc_w2, p_wBh, p_wBl, 128, 128, 128, totA);

    dim3 gconv(128, 2, B_);   // Cout=128 -> 2 groups of 64
    // local_conv chain: all NHWC after first stage
    conv3_mma<1, 0><<<gconv, 256>>>(feat0, p_wAh, p_wAl, lc_b1, p_tmp, 128, 128, 128);
    conv3_mma<0, 1><<<gconv, 256>>>(p_tmp, p_wBh, p_wBl, lc_b2, p_lf0, 128, 128, 128);
    conv3_mma<1, 0><<<gconv, 256>>>(feat1, p_wAh, p_wAl, lc_b1, p_tmp, 128, 128, 128);
    conv3_mma<0, 1><<<gconv, 256>>>(p_tmp, p_wBh, p_wBl, lc_b2, p_lf1, 128, 128, 128);
    transpose_nhwc<<<(B_ * C_ * HW) / 256, 256>>>(feat1, p_f1t);
    copy_kernel<<<(B_ * 2 * HW) / 256, 256>>>(flow_init, p_flow, B_ * 2 * HW);

    for (int it = 0; it < ITERS; it++) {
        warp_diff_norm<<<(B_ * HW) / 4, 128>>>(p_lf0, p_lf1, p_flow, p_feat);
        qk_gemm<<<dim3((B_ * HW) / 128, 2), 256>>>(p_feat, qw, qb, kw, kb, p_q, p_k);
        attn_kernel<<<(B_ * HW) / 4, 128>>>(p_q, p_k, p_flow, p_fi);
        conv3_small<2, 16, 1><<<(B_ * 16 * HW + 255) / 256, 256>>>(p_fi, fr_w1, fr_b1, p_d1);
        conv3_small<16, 16, 1><<<(B_ * 16 * HW + 255) / 256, 256>>>(p_d1, fr_w2, fr_b2, p_d2);
        conv3_small<16, 2, 3><<<(B_ * 2 * HW + 255) / 256, 256>>>(p_d2, fr_w3, fr_b3, p_flow);
    }

    // confidence head: build NHWC hcat (264 ch, padded)
    feat0_to_hcat<<<dim3(512, 4, B_), dim3(32, 8)>>>(feat0, p_hcat);
    warp_hcat_nhwc<<<(B_ * HW) / 4, 128>>>(p_f1t, p_flow, p_hcat);
    hcat_tail<<<(B_ * HW * 8) / 256, 256>>>(p_flow, p_hcat);

    int totC1 = 9 * HCATC * 128;
    int totC2 = 9 * 128 * 64;
    repack_w<<<(totC1 + 255) / 256, 256>>>(cf_w1, p_wAh, p_wAl, 258, HCATC, 128, totC1);
    repack_w<<<(totC2 + 255) / 256, 256>>>(cf_w2, p_wBh, p_wBl, 128, 128, 64, totC2);

    conv3_mma<1, 1><<<gconv, 256>>>(p_hcat, p_wAh, p_wAl, cf_b1, p_h1, HCATC, HCATC, 128);
    conv3_mma<1, 1><<<dim3(128, 1, B_), 256>>>(p_h1, p_wBh, p_wBl, cf_b2, p_h2, 128, 128, 64);
    conv_final_nhwc<<<(B_ * HW) / 4, 128>>>(p_h2, cf_w3, cf_b3, out + B_ * 2 * HW);

    // outputs: flow then conf
    copy_kernel<<<(B_ * 2 * HW) / 256, 256>>>(p_flow, out, B_ * 2 * HW);
}

// round 7
// speedup vs baseline: 1.8039x; 1.1226x over previous
#include <cuda_runtime.h>
#include <math.h>

#define HW   16384
#define W_   128
#define H_   128
#define C_   128
#define B_   2
#define ITERS 10
#define HCATC 264   // 258 padded to multiple of 8

// ---------------- scratch (static device globals; no allocation) ----------------
__device__ float g_tmp [B_*HW*C_];     // NHWC conv intermediate
__device__ float g_lf0 [B_*HW*C_];     // NHWC
__device__ float g_lf1 [B_*HW*C_];     // NHWC
__device__ float g_f1t [B_*HW*C_];     // feat1 NHWC
__device__ float g_feat[B_*HW*C_];     // NHWC
__device__ float g_q   [B_*HW*C_];     // NHWC
__device__ float g_k   [B_*HW*C_];     // NHWC
__device__ float g_fi  [B_*2*HW];      // NCHW
__device__ float g_d1  [B_*16*HW];
__device__ float g_d2  [B_*16*HW];
__device__ float g_flow[B_*2*HW];      // NCHW
__device__ float g_hcat[B_*HW*HCATC]; // NHWC padded
__device__ float g_h1  [B_*HW*C_];     // NHWC
__device__ float g_h2  [B_*HW*64];     // NHWC
// repacked tf32-split weights: [tap][ci_pad][co]
__device__ float g_wAhi[9*HCATC*C_];
__device__ float g_wAlo[9*HCATC*C_];
__device__ float g_wBhi[9*C_*C_];
__device__ float g_wBlo[9*C_*C_];
// q/k fused weights: [ci][256] (cols 0..127 = q, 128..255 = k)
__device__ float g_wQKh[C_*256];
__device__ float g_wQKl[C_*256];

__device__ __forceinline__ float gelu_f(float x) {
    return 0.5f * x * (1.0f + erff(x * 0.70710678118654752440f));
}

// ---------------- tf32 helpers ----------------
__device__ __forceinline__ unsigned cvt_tf32(float x) {
    unsigned r; asm("cvt.rna.tf32.f32 %0, %1;" : "=r"(r) : "f"(x)); return r;
}
__device__ __forceinline__ void mma_tf32(float* c, const unsigned* a, const unsigned* b) {
    asm volatile(
        "mma.sync.aligned.m16n8k8.row.col.f32.tf32.tf32.f32 "
        "{%0,%1,%2,%3}, {%4,%5,%6,%7}, {%8,%9}, {%0,%1,%2,%3};"
        : "+f"(c[0]), "+f"(c[1]), "+f"(c[2]), "+f"(c[3])
        : "r"(a[0]), "r"(a[1]), "r"(a[2]), "r"(a[3]), "r"(b[0]), "r"(b[1]));
}

// ---------------- weight repack + tf32 hi/lo split ----------------
__global__ void repack_w(const float* __restrict__ w, float* __restrict__ whi,
                         float* __restrict__ wlo, int Cin, int Cin_pad, int Cout, int total)
{
    int idx = blockIdx.x * blockDim.x + threadIdx.x;
    if (idx >= total) return;
    int co = idx % Cout;
    int r  = idx / Cout;
    int ci = r % Cin_pad;
    int tap = r / Cin_pad;
    float v = (ci < Cin) ? w[((size_t)co * Cin + ci) * 9 + tap] : 0.f;
    float h = __uint_as_float(cvt_tf32(v));
    float l = __uint_as_float(cvt_tf32(v - h));
    whi[idx] = h;
    wlo[idx] = l;
}

// qw/kw [d][c] -> fused [c][256]
__global__ void repack_qk(const float* __restrict__ qw, const float* __restrict__ kw,
                          float* __restrict__ wh, float* __restrict__ wl)
{
    int idx = blockIdx.x * blockDim.x + threadIdx.x;
    if (idx >= 128 * 256) return;
    int col = idx & 255;
    int ci  = idx >> 8;
    const float* src = (col < 128) ? qw : kw;
    float v = src[(col & 127) * 128 + ci];
    float h = __uint_as_float(cvt_tf32(v));
    float l = __uint_as_float(cvt_tf32(v - h));
    wh[idx] = h;
    wl[idx] = l;
}

// ---------------- tensor-core 3x3 conv v2 ----------------
// CTA: 16x8 px (M=128), N=64 co. 256 thr = 8 warps (4M x 2N). Dynamic smem:
//   s_ih[1620] s_il[1620]  : halo 18x10 px x 8 ci (stride 9), hi/lo pre-split
//   s_bh[5184] s_bl[5184]  : 9 taps x 8 ci x 64 co (stride 72)
#define CONV_SMEM_FLOATS (1620*2 + 5184*2)
template<int ACT, int INNHWC>
__global__ __launch_bounds__(256)
void conv3_mma(const float* __restrict__ in, const float* __restrict__ whi,
               const float* __restrict__ wlo, const float* __restrict__ bias,
               float* __restrict__ out, int Cin_pad, int inC, int CoutT)
{
    extern __shared__ float sm[];
    float* s_ih = sm;
    float* s_il = sm + 1620;
    float* s_bh = sm + 3240;
    float* s_bl = sm + 8424;

    int b   = blockIdx.z;
    int co0 = blockIdx.y << 6;
    int x0  = (blockIdx.x & 7) << 4;
    int y0  = (blockIdx.x >> 3) << 3;
    int tid = threadIdx.x;
    int lane = tid & 31, warp = tid >> 5;
    int warpM = warp >> 1, warpN = warp & 1;
    int qr = lane >> 2, qc = lane & 3;

    // precompute per-thread A-frag pixel bases (halo coords of r0 / r0+8 per mt)
    int baseA[2], baseB[2];
#pragma unroll
    for (int mt = 0; mt < 2; mt++) {
        int r0 = warpM * 32 + mt * 16 + qr;
        int r1 = r0 + 8;
        baseA[mt] = ((r0 >> 4) * 18 + (r0 & 15)) * 9;
        baseB[mt] = ((r1 >> 4) * 18 + (r1 & 15)) * 9;
    }

    float c[2][4][4];
#pragma unroll
    for (int mt = 0; mt < 2; mt++)
#pragma unroll
        for (int nt = 0; nt < 4; nt++)
#pragma unroll
            for (int i = 0; i < 4; i++) c[mt][nt][i] = 0.f;

    int nchunk = Cin_pad >> 3;
    for (int ch = 0; ch < nchunk; ch++) {
        int ci0 = ch << 3;
        __syncthreads();   // prev chunk's mma done

        // ---- stage input halo, hi/lo pre-split ----
        if (INNHWC) {
            for (int t = tid; t < 360; t += 256) {
                int pxi = t >> 1, half = t & 1;
                int iy = pxi / 18, ix = pxi - iy * 18;
                int gy = y0 - 1 + iy, gx = x0 - 1 + ix;
                float4 v = make_float4(0.f, 0.f, 0.f, 0.f);
                if ((unsigned)gy < 128u && (unsigned)gx < 128u)
                    v = *(const float4*)(in + ((size_t)(b * HW) + gy * W_ + gx) * inC + ci0 + half * 4);
                int base = (iy * 18 + ix) * 9 + half * 4;
                float vv[4] = {v.x, v.y, v.z, v.w};
#pragma unroll
                for (int j = 0; j < 4; j++) {
                    float h = __uint_as_float(cvt_tf32(vv[j]));
                    s_ih[base + j] = h;
                    s_il[base + j] = __uint_as_float(cvt_tf32(vv[j] - h));
                }
            }
        } else {
            for (int t = tid; t < 1440; t += 256) {
                int ix = t % 18, r = t / 18;
                int iy = r % 10, cc = r / 10;
                int gy = y0 - 1 + iy, gx = x0 - 1 + ix;
                float v = 0.f;
                if ((unsigned)gy < 128u && (unsigned)gx < 128u)
                    v = in[((size_t)(b * inC) + ci0 + cc) * HW + gy * W_ + gx];
                int base = (iy * 18 + ix) * 9 + cc;
                float h = __uint_as_float(cvt_tf32(v));
                s_ih[base] = h;
                s_il[base] = __uint_as_float(cvt_tf32(v - h));
            }
        }
        // ---- stage ALL 9 tap weight slabs ----
        for (int t = tid; t < 9 * 512; t += 256) {
            int tap = t >> 9;
            int r = t & 511;
            int kk = r >> 6, n = r & 63;
            size_t g = ((size_t)tap * Cin_pad + ci0 + kk) * CoutT + co0 + n;
            int s = tap * 576 + kk * 72 + n;
            s_bh[s] = whi[g];
            s_bl[s] = wlo[g];
        }
        __syncthreads();

#pragma unroll
        for (int tap = 0; tap < 9; tap++) {
            int ky = tap / 3, kx = tap - ky * 3;
            int off = (ky * 18 + kx) * 9;
            unsigned ahi[2][4], alo[2][4];
#pragma unroll
            for (int mt = 0; mt < 2; mt++) {
                int a0 = baseA[mt] + off, b0 = baseB[mt] + off;
                ahi[mt][0] = __float_as_uint(s_ih[a0 + qc]);
                ahi[mt][1] = __float_as_uint(s_ih[b0 + qc]);
                ahi[mt][2] = __float_as_uint(s_ih[a0 + qc + 4]);
                ahi[mt][3] = __float_as_uint(s_ih[b0 + qc + 4]);
                alo[mt][0] = __float_as_uint(s_il[a0 + qc]);
                alo[mt][1] = __float_as_uint(s_il[b0 + qc]);
                alo[mt][2] = __float_as_uint(s_il[a0 + qc + 4]);
                alo[mt][3] = __float_as_uint(s_il[b0 + qc + 4]);
            }
#pragma unroll
            for (int nt = 0; nt < 4; nt++) {
                int n = warpN * 32 + nt * 8 + qr;
                int sb = tap * 576 + n;
                unsigned bh[2], bl[2];
                bh[0] = __float_as_uint(s_bh[sb + qc * 72]);
                bh[1] = __float_as_uint(s_bh[sb + (qc + 4) * 72]);
                bl[0] = __float_as_uint(s_bl[sb + qc * 72]);
                bl[1] = __float_as_uint(s_bl[sb + (qc + 4) * 72]);
#pragma unroll
                for (int mt = 0; mt < 2; mt++) {
                    mma_tf32(c[mt][nt], ahi[mt], bh);
                    mma_tf32(c[mt][nt], ahi[mt], bl);
                    mma_tf32(c[mt][nt], alo[mt], bh);
                }
            }
        }
    }

    // ---- epilogue ----
#pragma unroll
    for (int nt = 0; nt < 4; nt++) {
        int col = co0 + warpN * 32 + nt * 8 + qc * 2;
        float b0 = bias[col], b1 = bias[col + 1];
#pragma unroll
        for (int mt = 0; mt < 2; mt++) {
            int r0 = warpM * 32 + mt * 16 + qr;
            int r1 = r0 + 8;
            int P0 = (y0 + (r0 >> 4)) * W_ + x0 + (r0 & 15);
            int P1 = (y0 + (r1 >> 4)) * W_ + x0 + (r1 & 15);
            float v0 = c[mt][nt][0] + b0, v1 = c[mt][nt][1] + b1;
            float v2 = c[mt][nt][2] + b0, v3 = c[mt][nt][3] + b1;
            if (ACT == 1) { v0 = gelu_f(v0); v1 = gelu_f(v1); v2 = gelu_f(v2); v3 = gelu_f(v3); }
            *(float2*)(out + ((size_t)(b * HW) + P0) * CoutT + col) = make_float2(v0, v1);
            *(float2*)(out + ((size_t)(b * HW) + P1) * CoutT + col) = make_float2(v2, v3);
        }
    }
}

// ---------------- q/k fused tf32 GEMM: out[p, :] = feat[p, :] @ W^T + b ----------------
// grid (256, 4): M-tile 128, col group 64 (cols<128 -> q, else k)
__global__ __launch_bounds__(256)
void qk_mma(const float* __restrict__ A, const float* __restrict__ wh,
            const float* __restrict__ wl, const float* __restrict__ Bq,
            const float* __restrict__ Bk, float* __restrict__ Qo, float* __restrict__ Ko)
{
    __shared__ float s_ah[8*136], s_al[8*136];
    __shared__ float s_bh[8*72],  s_bl[8*72];

    int m0  = blockIdx.x << 7;
    int co0 = blockIdx.y << 6;
    int tid = threadIdx.x;
    int lane = tid & 31, warp = tid >> 5;
    int warpM = warp >> 1, warpN = warp & 1;
    int qr = lane >> 2, qc = lane & 3;

    float c[2][4][4];
#pragma unroll
    for (int mt = 0; mt < 2; mt++)
#pragma unroll
        for (int nt = 0; nt < 4; nt++)
#pragma unroll
            for (int i = 0; i < 4; i++) c[mt][nt][i] = 0.f;

    int row_s = tid >> 1, half_s = tid & 1;

    for (int kc = 0; kc < 16; kc++) {
        __syncthreads();
        // stage A (128 rows x 8 k), split
        {
            float4 v = *(const float4*)(A + (size_t)(m0 + row_s) * 128 + kc * 8 + half_s * 4);
            float vv[4] = {v.x, v.y, v.z, v.w};
#pragma unroll
            for (int j = 0; j < 4; j++) {
                float h = __uint_as_float(cvt_tf32(vv[j]));
                s_ah[(half_s * 4 + j) * 136 + row_s] = h;
                s_al[(half_s * 4 + j) * 136 + row_s] = __uint_as_float(cvt_tf32(vv[j] - h));
            }
        }
        // stage B slab (8 k x 64 cols)
        for (int t = tid; t < 512; t += 256) {
            int kk = t >> 6, n = t & 63;
            size_t g = (size_t)(kc * 8 + kk) * 256 + co0 + n;
            s_bh[kk * 72 + n] = wh[g];
            s_bl[kk * 72 + n] = wl[g];
        }
        __syncthreads();

        unsigned ahi[2][4], alo[2][4];
#pragma unroll
        for (int mt = 0; mt < 2; mt++) {
            int r0 = warpM * 32 + mt * 16 + qr;
            int r1 = r0 + 8;
            ahi[mt][0] = __float_as_uint(s_ah[qc * 136 + r0]);
            ahi[mt][1] = __float_as_uint(s_ah[qc * 136 + r1]);
            ahi[mt][2] = __float_as_uint(s_ah[(qc + 4) * 136 + r0]);
            ahi[mt][3] = __float_as_uint(s_ah[(qc + 4) * 136 + r1]);
            alo[mt][0] = __float_as_uint(s_al[qc * 136 + r0]);
            alo[mt][1] = __float_as_uint(s_al[qc * 136 + r1]);
            alo[mt][2] = __float_as_uint(s_al[(qc + 4) * 136 + r0]);
            alo[mt][3] = __float_as_uint(s_al[(qc + 4) * 136 + r1]);
        }
#pragma unroll
        for (int nt = 0; nt < 4; nt++) {
            int n = warpN * 32 + nt * 8 + qr;
            unsigned bh[2], bl[2];
            bh[0] = __float_as_uint(s_bh[qc * 72 + n]);
            bh[1] = __float_as_uint(s_bh[(qc + 4) * 72 + n]);
            bl[0] = __float_as_uint(s_bl[qc * 72 + n]);
            bl[1] = __float_as_uint(s_bl[(qc + 4) * 72 + n]);
#pragma unroll
            for (int mt = 0; mt < 2; mt++) {
                mma_tf32(c[mt][nt], ahi[mt], bh);
                mma_tf32(c[mt][nt], ahi[mt], bl);
                mma_tf32(c[mt][nt], alo[mt], bh);
            }
        }
    }

    bool isQ = (co0 < 128);
    float* Out = isQ ? Qo : Ko;
    const float* Bs = isQ ? Bq : Bk;
#pragma unroll
    for (int nt = 0; nt < 4; nt++) {
        int col = co0 + warpN * 32 + nt * 8 + qc * 2;
        int ccol = col & 127;
        float b0 = Bs[ccol], b1 = Bs[ccol + 1];
#pragma unroll
        for (int mt = 0; mt < 2; mt++) {
            int r0 = m0 + warpM * 32 + mt * 16 + qr;
            int r1 = r0 + 8;
            *(float2*)(Out + (size_t)r0 * 128 + ccol) = make_float2(c[mt][nt][0] + b0, c[mt][nt][1] + b1);
            *(float2*)(Out + (size_t)r1 * 128 + ccol) = make_float2(c[mt][nt][2] + b0, c[mt][nt][3] + b1);
        }
    }
}

// ---------------- small direct 3x3 conv (tiny channel counts, NCHW) ----------------
template<int CIN, int COUT, int ACT>
__global__ void conv3_small(const float* __restrict__ in, const float* __restrict__ w,
                            const float* __restrict__ bias, float* __restrict__ out)
{
    int idx = blockIdx.x * blockDim.x + threadIdx.x;
    if (idx >= B_ * COUT * HW) return;
    int p  = idx % HW;
    int co = (idx / HW) % COUT;
    int b  = idx / (HW * COUT);
    int y = p >> 7, x = p & 127;

    float acc = bias[co];
    const float* ip = in + (size_t)b * CIN * HW;
    const float* wp = w + (size_t)co * CIN * 9;
#pragma unroll 4
    for (int ci = 0; ci < CIN; ci++) {
#pragma unroll
        for (int ky = 0; ky < 3; ky++) {
            int yy = y + ky - 1;
            if ((unsigned)yy < 128u) {
#pragma unroll
                for (int kx = 0; kx < 3; kx++) {
                    int xx = x + kx - 1;
                    if ((unsigned)xx < 128u)
                        acc += ip[ci * HW + yy * W_ + xx] * wp[ci * 9 + ky * 3 + kx];
                }
            }
        }
    }
    if (ACT == 1) acc = gelu_f(acc);
    if (ACT == 3) acc = out[idx] + acc;
    out[idx] = acc;
}

// ---------------- final conv 64->1 + sigmoid, NHWC input, warp per pixel ----------------
__global__ void conv_final_nhwc(const float* __restrict__ h2, const float* __restrict__ w,
                                const float* __restrict__ bias, float* __restrict__ outc)
{
    int gw   = (blockIdx.x * blockDim.x + threadIdx.x) >> 5;
    int lane = threadIdx.x & 31;
    int b = gw >> 14;
    int p = gw & (HW - 1);
    int y = p >> 7, x = p & 127;
    int c0 = lane * 2;

    float acc = 0.f;
#pragma unroll
    for (int tap = 0; tap < 9; tap++) {
        int ky = tap / 3, kx = tap - ky * 3;
        int yy = y + ky - 1, xx = x + kx - 1;
        if ((unsigned)yy < 128u && (unsigned)xx < 128u) {
            float2 v = *(const float2*)(h2 + ((size_t)(b * HW) + yy * W_ + xx) * 64 + c0);
            acc += v.x * w[c0 * 9 + tap] + v.y * w[(c0 + 1) * 9 + tap];
        }
    }
#pragma unroll
    for (int o = 16; o; o >>= 1) acc += __shfl_xor_sync(0xffffffffu, acc, o);
    if (lane == 0)
        outc[b * HW + p] = 1.0f / (1.0f + expf(-(acc + bias[0])));
}

// ---------------- warp-per-pixel: bilinear warp + diff + L2 normalize + (1 - .) ----------------
__global__ void warp_diff_norm(const float* __restrict__ lf0, const float* __restrict__ lf1,
                               const float* __restrict__ flow, float* __restrict__ feat)
{
    int gw   = (blockIdx.x * blockDim.x + threadIdx.x) >> 5;
    int lane = threadIdx.x & 31;
    int b = gw >> 14;
    int p = gw & (HW - 1);
    int y = p >> 7, x = p & 127;

    float fx = flow[(size_t)(b * 2) * HW + p];
    float fy = flow[(size_t)(b * 2 + 1) * HW + p];
    float xf = fminf(fmaxf((float)x + fx, 0.f), 127.f);
    float yf = fminf(fmaxf((float)y + fy, 0.f), 127.f);
    float x0f = floorf(xf), y0f = floorf(yf);
    int x0 = (int)x0f, y0 = (int)y0f;
    int x1 = min(x0 + 1, 127), y1 = min(y0 + 1, 127);
    float wx = xf - x0f, wy = yf - y0f;

    const float* base = lf1 + (size_t)b * HW * C_;
    int c4 = lane * 4;
    float4 v00 = *(const float4*)(base + (size_t)(y0 * W_ + x0) * C_ + c4);
    float4 v01 = *(const float4*)(base + (size_t)(y0 * W_ + x1) * C_ + c4);
    float4 v10 = *(const float4*)(base + (size_t)(y1 * W_ + x0) * C_ + c4);
    float4 v11 = *(const float4*)(base + (size_t)(y1 * W_ + x1) * C_ + c4);

    float w00 = (1.f - wx) * (1.f - wy), w01 = wx * (1.f - wy);
    float w10 = (1.f - wx) * wy,         w11 = wx * wy;

    float4 l0 = *(const float4*)(lf0 + (size_t)gw * C_ + c4);
    float dx0 = l0.x - (v00.x * w00 + v01.x * w01 + v10.x * w10 + v11.x * w11);
    float dx1 = l0.y - (v00.y * w00 + v01.y * w01 + v10.y * w10 + v11.y * w11);
    float dx2 = l0.z - (v00.z * w00 + v01.z * w01 + v10.z * w10 + v11.z * w11);
    float dx3 = l0.w - (v00.w * w00 + v01.w * w01 + v10.w * w10 + v11.w * w11);

    float ss = dx0 * dx0 + dx1 * dx1 + dx2 * dx2 + dx3 * dx3;
#pragma unroll
    for (int o = 16; o; o >>= 1) ss += __shfl_xor_sync(0xffffffffu, ss, o);
    float scale = 1.0f / fmaxf(sqrtf(ss), 1e-12f);

    float4 r = make_float4(1.f - dx0 * scale, 1.f - dx1 * scale,
                           1.f - dx2 * scale, 1.f - dx3 * scale);
    *(float4*)(feat + (size_t)gw * C_ + c4) = r;
}

// ---------------- warp-per-pixel: 25-tap local attention on flow ----------------
__global__ void attn_kernel(const float* __restrict__ q, const float* __restrict__ k,
                            const float* __restrict__ flow, float* __restrict__ fi)
{
    int gw   = (blockIdx.x * blockDim.x + threadIdx.x) >> 5;
    int lane = threadIdx.x & 31;
    int b = gw >> 14;
    int p = gw & (HW - 1);
    int y = p >> 7, x = p & 127;

    float4 qv = *(const float4*)(q + (size_t)gw * C_ + lane * 4);

    float myscore = -INFINITY;
#pragma unroll
    for (int t = 0; t < 25; t++) {
        int dy = t / 5 - 2, dx = t % 5 - 2;
        int yy = y + dy, xx = x + dx;
        float s = 0.f;
        if ((unsigned)yy < 128u && (unsigned)xx < 128u) {
            float4 kv = *(const float4*)(k + (size_t)(b * HW + yy * W_ + xx) * C_ + lane * 4);
            s = qv.x * kv.x + qv.y * kv.y + qv.z * kv.z + qv.w * kv.w;
        }
#pragma unroll
        for (int o = 16; o; o >>= 1) s += __shfl_xor_sync(0xffffffffu, s, o);
        if (lane == t) myscore = s * 0.088388347648318447f;
    }
    float m = myscore;
#pragma unroll
    for (int o = 16; o; o >>= 1) m = fmaxf(m, __shfl_xor_sync(0xffffffffu, m, o));
    float e = (lane < 25) ? expf(myscore - m) : 0.f;
    float ssum = e;
#pragma unroll
    for (int o = 16; o; o >>= 1) ssum += __shfl_xor_sync(0xffffffffu, ssum, o);
    float prob = e / ssum;

    float a0 = 0.f, a1 = 0.f;
    if (lane < 25) {
        int dy = lane / 5 - 2, dx = lane % 5 - 2;
        int yy = y + dy, xx = x + dx;
        if ((unsigned)yy < 128u && (unsigned)xx < 128u) {
            a0 = prob * flow[(size_t)(b * 2) * HW + yy * W_ + xx];
            a1 = prob * flow[(size_t)(b * 2 + 1) * HW + yy * W_ + xx];
        }
    }
#pragma unroll
    for (int o = 16; o; o >>= 1) {
        a0 += __shfl_xor_sync(0xffffffffu, a0, o);
        a1 += __shfl_xor_sync(0xffffffffu, a1, o);
    }
    if (lane == 0) {
        fi[(size_t)(b * 2) * HW + p]     = a0;
        fi[(size_t)(b * 2 + 1) * HW + p] = a1;
    }
}

// ---------------- warp feat1 (NHWC) -> hcat NHWC channels [128,256) ----------------
__global__ void warp_hcat_nhwc(const float* __restrict__ src, const float* __restrict__ flow,
                               float* __restrict__ hcat)
{
    int gw   = (blockIdx.x * blockDim.x + threadIdx.x) >> 5;
    int lane = threadIdx.x & 31;
    int b = gw >> 14;
    int p = gw & (HW - 1);
    int y = p >> 7, x = p & 127;

    float fx = flow[(size_t)(b * 2) * HW + p];
    float fy = flow[(size_t)(b * 2 + 1) * HW + p];
    float xf = fminf(fmaxf((float)x + fx, 0.f), 127.f);
    float yf = fminf(fmaxf((float)y + fy, 0.f), 127.f);
    float x0f = floorf(xf), y0f = floorf(yf);
    int x0 = (int)x0f, y0 = (int)y0f;
    int x1 = min(x0 + 1, 127), y1 = min(y0 + 1, 127);
    float wx = xf - x0f, wy = yf - y0f;

    const float* base = src + (size_t)b * HW * C_;
    int c4 = lane * 4;
    float4 v00 = *(const float4*)(base + (size_t)(y0 * W_ + x0) * C_ + c4);
    float4 v01 = *(const float4*)(base + (size_t)(y0 * W_ + x1) * C_ + c4);
    float4 v10 = *(const float4*)(base + (size_t)(y1 * W_ + x0) * C_ + c4);
    float4 v11 = *(const float4*)(base + (size_t)(y1 * W_ + x1) * C_ + c4);

    float w00 = (1.f - wx) * (1.f - wy), w01 = wx * (1.f - wy);
    float w10 = (1.f - wx) * wy,         w11 = wx * wy;

    float4 o;
    o.x = v00.x * w00 + v01.x * w01 + v10.x * w10 + v11.x * w11;
    o.y = v00.y * w00 + v01.y * w01 + v10.y * w10 + v11.y * w11;
    o.z = v00.z * w00 + v01.z * w01 + v10.z * w10 + v11.z * w11;
    o.w = v00.w * w00 + v01.w * w01 + v10.w * w10 + v11.w * w11;

    *(float4*)(hcat + ((size_t)(b * HW) + p) * HCATC + 128 + c4) = o;
}

// ---------------- misc ----------------
__global__ void copy_kernel(const float* __restrict__ in, float* __restrict__ out, int n)
{
    int i = blockIdx.x * blockDim.x + threadIdx.x;
    if (i < n) out[i] = in[i];
}

__global__ void transpose_nhwc(const float* __restrict__ in, float* __restrict__ out)
{
    int idx = blockIdx.x * blockDim.x + threadIdx.x;
    if (idx >= B_ * C_ * HW) return;
    int p = idx & (HW - 1);
    int c = (idx >> 14) & 127;
    int b = idx >> 21;
    out[((size_t)(b * HW) + p) * C_ + c] = in[idx];
}

// feat0 NCHW -> hcat NHWC channels [0,128), tiled transpose
__global__ void feat0_to_hcat(const float* __restrict__ feat0, float* __restrict__ hcat)
{
    __shared__ float tile[32][33];
    int p0 = blockIdx.x << 5, c0 = blockIdx.y << 5, b = blockIdx.z;
    for (int i = threadIdx.y; i < 32; i += 8)
        tile[i][threadIdx.x] = feat0[((size_t)(b * 128) + c0 + i) * HW + p0 + threadIdx.x];
    __syncthreads();
    for (int i = threadIdx.y; i < 32; i += 8)
        hcat[((size_t)(b * HW) + p0 + i) * HCATC + c0 + threadIdx.x] = tile[threadIdx.x][i];
}

// flow -> hcat channels [256,258); zero-pad [258,264)
__global__ void hcat_tail(const float* __restrict__ flow, float* __restrict__ hcat)
{
    int idx = blockIdx.x * blockDim.x + threadIdx.x;
    if (idx >= B_ * HW * 8) return;
    int c = idx & 7;
    int p = (idx >> 3) & (HW - 1);
    int b = idx >> 17;
    float v = (c < 2) ? flow[((size_t)(b * 2) + c) * HW + p] : 0.f;
    hcat[((size_t)(b * HW) + p) * HCATC + 256 + c] = v;
}

// ---------------- launch ----------------
extern "C" void kernel_launch(void* const* d_in, const int* in_sizes, int n_in,
                              void* d_out, int out_size)
{
    const float* feat0     = (const float*)d_in[0];
    const float* feat1     = (const float*)d_in[1];
    const float* flow_init = (const float*)d_in[2];
    const float* lc_w1 = (const float*)d_in[3];
    const float* lc_b1 = (const float*)d_in[4];
    const float* lc_w2 = (const float*)d_in[5];
    const float* lc_b2 = (const float*)d_in[6];
    const float* qw    = (const float*)d_in[7];
    const float* qb    = (const float*)d_in[8];
    const float* kw    = (const float*)d_in[9];
    const float* kb    = (const float*)d_in[10];
    const float* fr_w1 = (const float*)d_in[11];
    const float* fr_b1 = (const float*)d_in[12];
    const float* fr_w2 = (const float*)d_in[13];
    const float* fr_b2 = (const float*)d_in[14];
    const float* fr_w3 = (const float*)d_in[15];
    const float* fr_b3 = (const float*)d_in[16];
    const float* cf_w1 = (const float*)d_in[17];
    const float* cf_b1 = (const float*)d_in[18];
    const float* cf_w2 = (const float*)d_in[19];
    const float* cf_b2 = (const float*)d_in[20];
    const float* cf_w3 = (const float*)d_in[21];
    const float* cf_b3 = (const float*)d_in[22];
    float* out = (float*)d_out;

    float *p_tmp, *p_lf0, *p_lf1, *p_f1t, *p_feat, *p_q, *p_k;
    float *p_fi, *p_d1, *p_d2, *p_flow, *p_hcat, *p_h1, *p_h2;
    float *p_wAh, *p_wAl, *p_wBh, *p_wBl, *p_wQh, *p_wQl;
    cudaGetSymbolAddress((void**)&p_tmp,  g_tmp);
    cudaGetSymbolAddress((void**)&p_lf0,  g_lf0);
    cudaGetSymbolAddress((void**)&p_lf1,  g_lf1);
    cudaGetSymbolAddress((void**)&p_f1t,  g_f1t);
    cudaGetSymbolAddress((void**)&p_feat, g_feat);
    cudaGetSymbolAddress((void**)&p_q,    g_q);
    cudaGetSymbolAddress((void**)&p_k,    g_k);
    cudaGetSymbolAddress((void**)&p_fi,   g_fi);
    cudaGetSymbolAddress((void**)&p_d1,   g_d1);
    cudaGetSymbolAddress((void**)&p_d2,   g_d2);
    cudaGetSymbolAddress((void**)&p_flow, g_flow);
    cudaGetSymbolAddress((void**)&p_hcat, g_hcat);
    cudaGetSymbolAddress((void**)&p_h1,   g_h1);
    cudaGetSymbolAddress((void**)&p_h2,   g_h2);
    cudaGetSymbolAddress((void**)&p_wAh,  g_wAhi);
    cudaGetSymbolAddress((void**)&p_wAl,  g_wAlo);
    cudaGetSymbolAddress((void**)&p_wBh,  g_wBhi);
    cudaGetSymbolAddress((void**)&p_wBl,  g_wBlo);
    cudaGetSymbolAddress((void**)&p_wQh,  g_wQKh);
    cudaGetSymbolAddress((void**)&p_wQl,  g_wQKl);

    const int CONV_SMEM = CONV_SMEM_FLOATS * 4;
    cudaFuncSetAttribute(conv3_mma<1, 0>, cudaFuncAttributeMaxDynamicSharedMemorySize, CONV_SMEM);
    cudaFuncSetAttribute(conv3_mma<0, 1>, cudaFuncAttributeMaxDynamicSharedMemorySize, CONV_SMEM);
    cudaFuncSetAttribute(conv3_mma<1, 1>, cudaFuncAttributeMaxDynamicSharedMemorySize, CONV_SMEM);

    // repack weights (local_conv + q/k once)
    int totA = 9 * 128 * 128;
    repack_w<<<(totA + 255) / 256, 256>>>(lc_w1, p_wAh, p_wAl, 128, 128, 128, totA);
    repack_w<<<(totA + 255) / 256, 256>>>(lc_w2, p_wBh, p_wBl, 128, 128, 128, totA);
    repack_qk<<<(128 * 256) / 256, 256>>>(qw, kw, p_wQh, p_wQl);

    dim3 gconv(128, 2, B_);
    conv3_mma<1, 0><<<gconv, 256, CONV_SMEM>>>(feat0, p_wAh, p_wAl, lc_b1, p_tmp, 128, 128, 128);
    conv3_mma<0, 1><<<gconv, 256, CONV_SMEM>>>(p_tmp, p_wBh, p_wBl, lc_b2, p_lf0, 128, 128, 128);
    conv3_mma<1, 0><<<gconv, 256, CONV_SMEM>>>(feat1, p_wAh, p_wAl, lc_b1, p_tmp, 128, 128, 128);
    conv3_mma<0, 1><<<gconv, 256, CONV_SMEM>>>(p_tmp, p_wBh, p_wBl, lc_b2, p_lf1, 128, 128, 128);
    transpose_nhwc<<<(B_ * C_ * HW) / 256, 256>>>(feat1, p_f1t);
    copy_kernel<<<(B_ * 2 * HW) / 256, 256>>>(flow_init, p_flow, B_ * 2 * HW);

    for (int it = 0; it < ITERS; it++) {
        warp_diff_norm<<<(B_ * HW) / 4, 128>>>(p_lf0, p_lf1, p_flow, p_feat);
        qk_mma<<<dim3(256, 4), 256>>>(p_feat, p_wQh, p_wQl, qb, kb, p_q, p_k);
        attn_kernel<<<(B_ * HW) / 4, 128>>>(p_q, p_k, p_flow, p_fi);
        conv3_small<2, 16, 1><<<(B_ * 16 * HW + 255) / 256, 256>>>(p_fi, fr_w1, fr_b1, p_d1);
        conv3_small<16, 16, 1><<<(B_ * 16 * HW + 255) / 256, 256>>>(p_d1, fr_w2, fr_b2, p_d2);
        conv3_small<16, 2, 3><<<(B_ * 2 * HW + 255) / 256, 256>>>(p_d2, fr_w3, fr_b3, p_flow);
    }

    // confidence head
    feat0_to_hcat<<<dim3(512, 4, B_), dim3(32, 8)>>>(feat0, p_hcat);
    warp_hcat_nhwc<<<(B_ * HW) / 4, 128>>>(p_f1t, p_flow, p_hcat);
    hcat_tail<<<(B_ * HW * 8) / 256, 256>>>(p_flow, p_hcat);

    int totC1 = 9 * HCATC * 128;
    int totC2 = 9 * 128 * 64;
    repack_w<<<(totC1 + 255) / 256, 256>>>(cf_w1, p_wAh, p_wAl, 258, HCATC, 128, totC1);
    repack_w<<<(totC2 + 255) / 256, 256>>>(cf_w2, p_wBh, p_wBl, 128, 128, 64, totC2);

    conv3_mma<1, 1><<<gconv, 256, CONV_SMEM>>>(p_hcat, p_wAh, p_wAl, cf_b1, p_h1, HCATC, HCATC, 128);
    conv3_mma<1, 1><<<dim3(128, 1, B_), 256, CONV_SMEM>>>(p_h1, p_wBh, p_wBl, cf_b2, p_h2, 128, 128, 64);
    conv_final_nhwc<<<(B_ * HW) / 4, 128>>>(p_h2, cf_w3, cf_b3, out + B_ * 2 * HW);

    // outputs: flow then conf
    copy_kernel<<<(B_ * 2 * HW) / 256, 256>>>(p_flow, out, B_ * 2 * HW);
}